// round 13
// baseline (speedup 1.0000x reference)
#include <cuda_runtime.h>
#include <cuda_bf16.h>
#include <cuda_fp16.h>
#include <math.h>

#define NB 4
#define NS 4096
#define NN 128
#define TD 1024
#define SD 512
#define PD 512
#define NH 4
#define HD 128
#define NTOK (NB*NS)
#define NTILES 1024

// ---------------- static device scratch (no runtime alloc allowed) ----------
__device__ __align__(16) __nv_bfloat16 g_Ahi[NTOK*TD];        // 32 MB
__device__ __align__(16) __nv_bfloat16 g_Alo[NTOK*TD];        // 32 MB
__device__ __align__(16) float g_sn[NB*NN*SD];                // 1 MB
__device__ __align__(16) float g_kfull[NB*NN*PD];             // 1 MB
__device__ float g_qpart[16*PD];
__device__ float g_qconst[PD];
__device__ float g_biasv[NB*PD];
__device__ __align__(16) __nv_bfloat16 g_Chi[NB*NH*TD*HD];    // 4 MB  [b][h][k][n]
__device__ __align__(16) __nv_bfloat16 g_Clo[NB*NH*TD*HD];    // 4 MB
__device__ __align__(16) __half g_w[(size_t)NB*NH*NS*NN];     // 16 MB (fp16 weights)
__device__ float g_entpart[2048];
__device__ unsigned g_tile;

// ---------------- PTX helpers ----------------------------------------------
__device__ __forceinline__ void ldsm4(unsigned* r, const void* p) {
    unsigned a = (unsigned)__cvta_generic_to_shared(p);
    asm volatile("ldmatrix.sync.aligned.m8n8.x4.shared.b16 {%0,%1,%2,%3}, [%4];"
                 : "=r"(r[0]), "=r"(r[1]), "=r"(r[2]), "=r"(r[3]) : "r"(a));
}
__device__ __forceinline__ void ldsm4t(unsigned* r, const void* p) {
    unsigned a = (unsigned)__cvta_generic_to_shared(p);
    asm volatile("ldmatrix.sync.aligned.m8n8.x4.trans.shared.b16 {%0,%1,%2,%3}, [%4];"
                 : "=r"(r[0]), "=r"(r[1]), "=r"(r[2]), "=r"(r[3]) : "r"(a));
}
__device__ __forceinline__ void mma_bf16(float c[4], const unsigned a[4], const unsigned b[2]) {
    asm volatile("mma.sync.aligned.m16n8k16.row.col.f32.bf16.bf16.f32 "
                 "{%0,%1,%2,%3},{%4,%5,%6,%7},{%8,%9},{%0,%1,%2,%3};"
                 : "+f"(c[0]), "+f"(c[1]), "+f"(c[2]), "+f"(c[3])
                 : "r"(a[0]), "r"(a[1]), "r"(a[2]), "r"(a[3]), "r"(b[0]), "r"(b[1]));
}
__device__ __forceinline__ void cpa16(void* s, const void* g) {
    unsigned sa = (unsigned)__cvta_generic_to_shared(s);
    asm volatile("cp.async.cg.shared.global [%0],[%1],16;" :: "r"(sa), "l"(g) : "memory");
}
#define CP_COMMIT() asm volatile("cp.async.commit_group;" ::: "memory")
#define CP_WAIT1()  asm volatile("cp.async.wait_group 1;"  ::: "memory")
#define CP_WAIT0()  asm volatile("cp.async.wait_group 0;"  ::: "memory")

// ============================================================================
// L1 prep1: tokln warp-per-row (2048) | state LN (512) | qconst parts (32)
// ============================================================================
__global__ void prep1_kernel(const float* __restrict__ tok, float* __restrict__ out_tok,
                             const float* __restrict__ st,
                             const float* __restrict__ lnsg, const float* __restrict__ lnsb,
                             const float* __restrict__ Wq, const float* __restrict__ bt) {
    int bid = blockIdx.x, t = threadIdx.x;
    if (bid < 2048) {
        if (bid == 0 && t == 0) g_tile = 0;    // reset work-steal counter
        int w = t >> 5, l = t & 31;
        int row = bid * 8 + w;
        const float4* rp = (const float4*)(tok + (size_t)row * TD);
        float4* wp = (float4*)(out_tok + (size_t)row * TD);
        float4 x[8];
        #pragma unroll
        for (int j = 0; j < 8; j++) x[j] = rp[j * 32 + l];
        #pragma unroll
        for (int j = 0; j < 8; j++) wp[j * 32 + l] = x[j];   // passthrough
        float p = 0.f;
        #pragma unroll
        for (int j = 0; j < 8; j++) p += (x[j].x + x[j].y) + (x[j].z + x[j].w);
        #pragma unroll
        for (int o = 16; o; o >>= 1) p += __shfl_xor_sync(~0u, p, o);
        float mu = p * (1.f / TD);
        float v = 0.f;
        #pragma unroll
        for (int j = 0; j < 8; j++) {
            float a = x[j].x - mu, b = x[j].y - mu, c = x[j].z - mu, d = x[j].w - mu;
            v += a*a + b*b + c*c + d*d;
        }
        #pragma unroll
        for (int o = 16; o; o >>= 1) v += __shfl_xor_sync(~0u, v, o);
        float r = rsqrtf(v * (1.f / TD) + 1e-5f);
        #pragma unroll
        for (int j = 0; j < 8; j++) {
            float z0 = (x[j].x - mu) * r, z1 = (x[j].y - mu) * r;
            float z2 = (x[j].z - mu) * r, z3 = (x[j].w - mu) * r;
            union { __nv_bfloat16 b[4]; uint2 u; } hz, lz;
            hz.b[0] = __float2bfloat16(z0); lz.b[0] = __float2bfloat16(z0 - __bfloat162float(hz.b[0]));
            hz.b[1] = __float2bfloat16(z1); lz.b[1] = __float2bfloat16(z1 - __bfloat162float(hz.b[1]));
            hz.b[2] = __float2bfloat16(z2); lz.b[2] = __float2bfloat16(z2 - __bfloat162float(hz.b[2]));
            hz.b[3] = __float2bfloat16(z3); lz.b[3] = __float2bfloat16(z3 - __bfloat162float(hz.b[3]));
            int idx = (j * 32 + l) * 4;
            *reinterpret_cast<uint2*>(&g_Ahi[(size_t)row * TD + idx]) = hz.u;
            *reinterpret_cast<uint2*>(&g_Alo[(size_t)row * TD + idx]) = lz.u;
        }
    } else if (bid < 2048 + NB * NN) {
        int row = bid - 2048;
        const float2* rp = (const float2*)(st + (size_t)row * SD);
        float2 x = rp[t];
        __shared__ float red2[8];
        __shared__ float z_mu, z_rstd;
        float p = x.x + x.y;
        #pragma unroll
        for (int o = 16; o; o >>= 1) p += __shfl_xor_sync(~0u, p, o);
        if ((t & 31) == 0) red2[t >> 5] = p;
        __syncthreads();
        if (t == 0) { float s = 0;
            #pragma unroll
            for (int i = 0; i < 8; i++) s += red2[i]; z_mu = s * (1.f / SD); }
        __syncthreads();
        float mu = z_mu;
        float d0 = x.x - mu, d1 = x.y - mu;
        p = d0*d0 + d1*d1;
        #pragma unroll
        for (int o = 16; o; o >>= 1) p += __shfl_xor_sync(~0u, p, o);
        if ((t & 31) == 0) red2[t >> 5] = p;
        __syncthreads();
        if (t == 0) { float s = 0;
            #pragma unroll
            for (int i = 0; i < 8; i++) s += red2[i]; z_rstd = rsqrtf(s * (1.f / SD) + 1e-5f); }
        __syncthreads();
        float r = z_rstd;
        int c = t * 2;
        float2 y;
        y.x = d0 * r * lnsg[c]     + lnsb[c];
        y.y = d1 * r * lnsg[c + 1] + lnsb[c + 1];
        ((float2*)(g_sn + (size_t)row * SD))[t] = y;
    } else {
        int idx = bid - 2048 - NB * NN;      // 0..31
        int p = (idx & 1) * 256 + t;
        int k0 = (idx >> 1) * 64;
        float acc = 0.f;
        #pragma unroll 8
        for (int kk = 0; kk < 64; kk++) acc += bt[k0 + kk] * Wq[(size_t)(k0 + kk) * PD + p];
        g_qpart[(idx >> 1) * PD + p] = acc;
    }
}

// ============================================================================
// L2 prepB: kproj (32 blocks) | qreduce (2 blocks)
// ============================================================================
__global__ void prepB_kernel(const float* __restrict__ Wk, const float* __restrict__ bk,
                             const float* __restrict__ bq) {
    int bid = blockIdx.x, t = threadIdx.x;
    if (bid < 32) {
        int r0 = (bid & 7) * 64, p0 = (bid >> 3) * 128;
        __shared__ float sSn[64 * 33];
        __shared__ float sWk[32 * 128];
        int tr = t >> 4, tp = t & 15;
        float acc[4][8];
        #pragma unroll
        for (int i = 0; i < 4; i++)
            #pragma unroll
            for (int j = 0; j < 8; j++) acc[i][j] = 0.f;
        for (int c0 = 0; c0 < SD; c0 += 32) {
            for (int idx = t; idx < 64 * 32; idx += 256) {
                int rr = idx >> 5, cc = idx & 31;
                sSn[rr * 33 + cc] = g_sn[(size_t)(r0 + rr) * SD + c0 + cc];
            }
            for (int idx = t; idx < 32 * 128; idx += 256) {
                int cc = idx >> 7, pp = idx & 127;
                sWk[cc * 128 + pp] = Wk[(size_t)(c0 + cc) * PD + p0 + pp];
            }
            __syncthreads();
            for (int cc = 0; cc < 32; cc++) {
                float a0 = sSn[(tr*4+0)*33+cc], a1 = sSn[(tr*4+1)*33+cc];
                float a2 = sSn[(tr*4+2)*33+cc], a3 = sSn[(tr*4+3)*33+cc];
                #pragma unroll
                for (int pp = 0; pp < 8; pp++) {
                    float w = sWk[cc * 128 + tp * 8 + pp];
                    acc[0][pp] += a0 * w; acc[1][pp] += a1 * w;
                    acc[2][pp] += a2 * w; acc[3][pp] += a3 * w;
                }
            }
            __syncthreads();
        }
        #pragma unroll
        for (int rr = 0; rr < 4; rr++)
            #pragma unroll
            for (int pp = 0; pp < 8; pp++) {
                int p = p0 + tp * 8 + pp;
                g_kfull[(size_t)(r0 + tr*4 + rr) * PD + p] = acc[rr][pp] + bk[p];
            }
    } else {
        int p = (bid - 32) * 256 + t;
        float s = bq[p];
        #pragma unroll
        for (int j = 0; j < 16; j++) s += g_qpart[j * PD + p];
        g_qconst[p] = s;
    }
}

// ============================================================================
// L3 prepC: cbuild 4kx8n register-blocked (256 blocks) | biasv (8 blocks)
// ============================================================================
__global__ void prepC_kernel(const float* __restrict__ Wq, const float* __restrict__ gt,
                             const float* __restrict__ temp) {
    int bid = blockIdx.x, t = threadIdx.x;
    if (bid < 256) {
        int kt = bid & 15, h = (bid >> 4) & 3, b = bid >> 6;
        int k0 = kt * 64;
        float invt = 1.f / fmaxf(temp[0], 0.1f);
        __shared__ float sWg[64 * 33];
        __shared__ float sKp[32 * 133];
        int tr = t >> 4, tp = t & 15;
        float acc[4][8];
        #pragma unroll
        for (int i = 0; i < 4; i++)
            #pragma unroll
            for (int j = 0; j < 8; j++) acc[i][j] = 0.f;
        int dd0 = t & 31, grp = t >> 5;
        for (int dc = 0; dc < HD; dc += 32) {
            #pragma unroll
            for (int kk = grp; kk < 64; kk += 8)
                sWg[kk * 33 + dd0] = Wq[(size_t)(k0 + kk) * PD + h * HD + dc + dd0] * gt[k0 + kk];
            #pragma unroll
            for (int n = grp; n < 128; n += 8)
                sKp[dd0 * 133 + n] = g_kfull[((size_t)(b * NN + n)) * PD + h * HD + dc + dd0] * invt;
            __syncthreads();
            #pragma unroll
            for (int dd = 0; dd < 32; dd++) {
                float a0 = sWg[(tr * 4 + 0) * 33 + dd];
                float a1 = sWg[(tr * 4 + 1) * 33 + dd];
                float a2 = sWg[(tr * 4 + 2) * 33 + dd];
                float a3 = sWg[(tr * 4 + 3) * 33 + dd];
                #pragma unroll
                for (int pp = 0; pp < 8; pp++) {
                    float w = sKp[dd * 133 + tp + 16 * pp];
                    acc[0][pp] += a0 * w; acc[1][pp] += a1 * w;
                    acc[2][pp] += a2 * w; acc[3][pp] += a3 * w;
                }
            }
            __syncthreads();
        }
        #pragma unroll
        for (int i = 0; i < 4; i++) {
            int k = k0 + tr * 4 + i;
            size_t rowb = ((size_t)(b * NH + h) * TD + k) * HD;
            #pragma unroll
            for (int pp = 0; pp < 8; pp++) {
                int n = tp + 16 * pp;
                float v = acc[i][pp];
                __nv_bfloat16 hi = __float2bfloat16(v);
                g_Chi[rowb + n] = hi;
                g_Clo[rowb + n] = __float2bfloat16(v - __bfloat162float(hi));
            }
        }
    } else {
        int gi = (bid - 256) * 256 + t;
        int b = gi >> 9, r = gi & 511;
        int h = r >> 7, n = r & 127;
        float invt = 1.f / fmaxf(temp[0], 0.1f);
        const float* kp = &g_kfull[((size_t)(b * NN + n)) * PD + h * HD];
        const float* qc = &g_qconst[h * HD];
        float acc = 0.f;
        for (int d = 0; d < HD; d++) acc += qc[d] * kp[d];
        g_biasv[b * PD + r] = acc * invt;
    }
}

// ============================================================================
// L4 main (PROFILED): persistent work-stealing GEMM + per-head softmax
// 296 blocks, 256 thr (8 warps: 2m x 4n = 32x32 warp tiles), BM=64 BN=128 BK=64
// ============================================================================
__global__ void __launch_bounds__(256, 2) main_kernel() {
    extern __shared__ char smem[];
    const int STG = 49152;   // per-stage: Ahi 8K | Alo 8K | Chi 16K | Clo 16K
    __shared__ float sBias[128];
    __shared__ float sMax[64][4], sSum[64][4];
    __shared__ unsigned sTile;
    int t = threadIdx.x, l = t & 31, w = t >> 5;
    int wm = w >> 2, wn = w & 3;

    // thread-invariant fragment indexing (2m x 4n warp tile: rows 32, cols 32)
    int mA0 = wm * 32 + (l & 15);          // r=0 m16 tile row
    int selA = l >> 4;
    int aX = mA0 & 7;                      // (+16 for r=1 keeps &7)
    int kb = ((l >> 3) & 1) * 8 + (l & 7);
    int cpB[2];
    #pragma unroll
    for (int p = 0; p < 2; p++) {
        int c = wn * 4 + p * 2 + (l >> 4);
        cpB[p] = (c & 8) | ((c & 7) ^ (l & 7));
    }
    int rl = l >> 2;                       // row within 8-group
    int cl = (l & 3) * 2;                  // col pair within n8

    while (true) {
        if (t == 0) sTile = atomicAdd(&g_tile, 1u);
        __syncthreads();
        unsigned tile = sTile;
        if (tile >= NTILES) break;
        int stile = tile & 63, h = (tile >> 6) & 3, b = tile >> 8;

        if (t < 128) sBias[t] = g_biasv[b * PD + h * HD + t];

        const __nv_bfloat16* gA_hi = g_Ahi + ((size_t)(b * NS + stile * 64)) * TD;
        const __nv_bfloat16* gA_lo = g_Alo + ((size_t)(b * NS + stile * 64)) * TD;
        const __nv_bfloat16* gC_hi = g_Chi + (size_t)(b * NH + h) * TD * HD;
        const __nv_bfloat16* gC_lo = g_Clo + (size_t)(b * NH + h) * TD * HD;

        auto loadStage = [&](int s, int kk) {
            char* base = smem + s * STG;
            #pragma unroll
            for (int i = 0; i < 2; i++) {
                int cid = t + i * 256, m = cid >> 3, c = cid & 7;
                int cc = c ^ (m & 7);
                cpa16(base + m * 128 + cc * 16,        gA_hi + (size_t)m * TD + kk + c * 8);
                cpa16(base + 8192 + m * 128 + cc * 16, gA_lo + (size_t)m * TD + kk + c * 8);
            }
            #pragma unroll
            for (int i = 0; i < 4; i++) {
                int cid = t + i * 256, k = cid >> 4, c = cid & 15;
                int cc = (c & 8) | ((c & 7) ^ (k & 7));
                cpa16(base + 16384 + k * 256 + cc * 16, gC_hi + (size_t)(kk + k) * HD + c * 8);
                cpa16(base + 32768 + k * 256 + cc * 16, gC_lo + (size_t)(kk + k) * HD + c * 8);
            }
        };

        float acc[8][4];   // [r*4+q][..]  r in 2 (m16), q in 4 (n8)
        #pragma unroll
        for (int j = 0; j < 8; j++)
            #pragma unroll
            for (int q = 0; q < 4; q++) acc[j][q] = 0.f;

        loadStage(0, 0);
        CP_COMMIT();

        for (int it = 0; it < 16; ++it) {
            if (it + 1 < 16) loadStage((it + 1) & 1, (it + 1) * 64);
            CP_COMMIT();
            CP_WAIT1();
            __syncthreads();
            char* base = smem + (it & 1) * STG;
            #pragma unroll
            for (int ks = 0; ks < 4; ++ks) {
                unsigned ahi[8], alo[8];
                int aoff = mA0 * 128 + (((ks * 2 + selA) ^ aX) << 4);
                ldsm4(&ahi[0], base + aoff);
                ldsm4(&ahi[4], base + aoff + 2048);           // r=1: +16 rows
                ldsm4(&alo[0], base + 8192 + aoff);
                ldsm4(&alo[4], base + 8192 + aoff + 2048);
                unsigned bhi[8], blo[8];
                int rowOff = (ks * 16 + kb) * 256;
                #pragma unroll
                for (int p = 0; p < 2; p++) {
                    ldsm4t(&bhi[p * 4], base + 16384 + rowOff + cpB[p] * 16);
                    ldsm4t(&blo[p * 4], base + 32768 + rowOff + cpB[p] * 16);
                }
                #pragma unroll
                for (int r = 0; r < 2; r++)
                    #pragma unroll
                    for (int q = 0; q < 4; q++) {
                        mma_bf16(acc[r * 4 + q], &ahi[r * 4], &bhi[q * 2]);
                        mma_bf16(acc[r * 4 + q], &ahi[r * 4], &blo[q * 2]);
                        mma_bf16(acc[r * 4 + q], &alo[r * 4], &bhi[q * 2]);
                    }
            }
            __syncthreads();
        }

        // ---- epilogue: +bias, per-head softmax over n (4 wn warps per row) --
        #pragma unroll
        for (int j = 0; j < 8; j++) {
            int q = j & 3;
            float b0 = sBias[wn * 32 + q * 8 + cl];
            float b1 = sBias[wn * 32 + q * 8 + cl + 1];
            acc[j][0] += b0; acc[j][1] += b1; acc[j][2] += b0; acc[j][3] += b1;
        }
        // 4 rows per thread: R[ri] = wm*32 + ri*8 + rl  (ri = r*2 + half)
        float mx[4];
        #pragma unroll
        for (int ri = 0; ri < 4; ri++) {
            int r = ri >> 1, h2 = (ri & 1) * 2;
            float m = -1e30f;
            #pragma unroll
            for (int q = 0; q < 4; q++)
                m = fmaxf(m, fmaxf(acc[r * 4 + q][h2], acc[r * 4 + q][h2 + 1]));
            m = fmaxf(m, __shfl_xor_sync(~0u, m, 1));
            m = fmaxf(m, __shfl_xor_sync(~0u, m, 2));
            mx[ri] = m;
        }
        if ((l & 3) == 0) {
            #pragma unroll
            for (int ri = 0; ri < 4; ri++) sMax[wm * 32 + ri * 8 + rl][wn] = mx[ri];
        }
        __syncthreads();
        float sm[4];
        #pragma unroll
        for (int ri = 0; ri < 4; ri++) {
            float* p = sMax[wm * 32 + ri * 8 + rl];
            mx[ri] = fmaxf(fmaxf(p[0], p[1]), fmaxf(p[2], p[3]));
            sm[ri] = 0.f;
        }
        #pragma unroll
        for (int ri = 0; ri < 4; ri++) {
            int r = ri >> 1, h2 = (ri & 1) * 2;
            #pragma unroll
            for (int q = 0; q < 4; q++) {
                acc[r * 4 + q][h2]     = __expf(acc[r * 4 + q][h2]     - mx[ri]);
                acc[r * 4 + q][h2 + 1] = __expf(acc[r * 4 + q][h2 + 1] - mx[ri]);
                sm[ri] += acc[r * 4 + q][h2] + acc[r * 4 + q][h2 + 1];
            }
            sm[ri] += __shfl_xor_sync(~0u, sm[ri], 1);
            sm[ri] += __shfl_xor_sync(~0u, sm[ri], 2);
        }
        if ((l & 3) == 0) {
            #pragma unroll
            for (int ri = 0; ri < 4; ri++) sSum[wm * 32 + ri * 8 + rl][wn] = sm[ri];
        }
        __syncthreads();
        __half* wout = g_w + ((size_t)(b * NH + h) * NS + stile * 64) * NN;
        #pragma unroll
        for (int ri = 0; ri < 4; ri++) {
            int row = wm * 32 + ri * 8 + rl;
            float* p = sSum[row];
            float inv = 1.f / ((p[0] + p[1]) + (p[2] + p[3]));
            int r = ri >> 1, h2 = (ri & 1) * 2;
            #pragma unroll
            for (int q = 0; q < 4; q++) {
                *(__half2*)(wout + (size_t)row * NN + wn * 32 + q * 8 + cl) =
                    __floats2half2_rn(acc[r * 4 + q][h2] * inv, acc[r * 4 + q][h2 + 1] * inv);
            }
        }
        __syncthreads();   // sMax/sSum/sBias reuse next tile
    }
}

// ============================================================================
// L5 meanent: head-mean + entropy partials (warp-per-row, fp16 reads)
// ============================================================================
__global__ void meanent_kernel(float* __restrict__ out_rout) {
    int t = threadIdx.x, w = t >> 5, l = t & 31;
    int row = blockIdx.x * 8 + w;
    int b = row >> 12, s = row & 4095;
    size_t hs = (size_t)NS * NN;
    size_t base = ((size_t)(b * NH) * NS + s) * NN + l * 4;
    float a0 = 0.f, a1 = 0.f, a2 = 0.f, a3 = 0.f;
    #pragma unroll
    for (int h = 0; h < NH; h++) {
        const __half2* p = (const __half2*)(g_w + base + h * hs);
        float2 x = __half22float2(p[0]);
        float2 y = __half22float2(p[1]);
        a0 += x.x; a1 += x.y; a2 += y.x; a3 += y.y;
    }
    float4 v = make_float4(a0 * 0.25f, a1 * 0.25f, a2 * 0.25f, a3 * 0.25f);
    *(float4*)(out_rout + (size_t)row * NN + l * 4) = v;
    float c = v.x * __logf(v.x + 1e-8f) + v.y * __logf(v.y + 1e-8f)
            + v.z * __logf(v.z + 1e-8f) + v.w * __logf(v.w + 1e-8f);
    #pragma unroll
    for (int o = 16; o; o >>= 1) c += __shfl_xor_sync(~0u, c, o);
    __shared__ float red[8];
    if (l == 0) red[w] = c;
    __syncthreads();
    if (t == 0) {
        float s2 = 0.f;
        #pragma unroll
        for (int i = 0; i < 8; i++) s2 += red[i];
        g_entpart[blockIdx.x] = s2;
    }
}

// ============================================================================
// L6 fin: final reduce of 2048 partials -> loss scalar
// ============================================================================
__global__ void fin_kernel(float* __restrict__ out) {
    int t = threadIdx.x;
    float s = 0.f;
    #pragma unroll
    for (int i = 0; i < 8; i++) s += g_entpart[i * 256 + t];
    #pragma unroll
    for (int o = 16; o; o >>= 1) s += __shfl_xor_sync(~0u, s, o);
    __shared__ float red[8];
    if ((t & 31) == 0) red[t >> 5] = s;
    __syncthreads();
    if (t == 0) {
        float tot = 0.f;
        #pragma unroll
        for (int i = 0; i < 8; i++) tot += red[i];
        out[0] = tot * (0.01f / (float)NTOK);
    }
}

// ---------------- launch (single stream) -------------------------------------
extern "C" void kernel_launch(void* const* d_in, const int* in_sizes, int n_in,
                              void* d_out, int out_size) {
    (void)in_sizes; (void)n_in; (void)out_size;
    const float* tokens = (const float*)d_in[0];
    const float* states = (const float*)d_in[1];
    const float* ln_t_g = (const float*)d_in[2];
    const float* ln_t_b = (const float*)d_in[3];
    const float* ln_s_g = (const float*)d_in[4];
    const float* ln_s_b = (const float*)d_in[5];
    const float* Wq     = (const float*)d_in[6];
    const float* bq     = (const float*)d_in[7];
    const float* Wk     = (const float*)d_in[8];
    const float* bk     = (const float*)d_in[9];
    const float* temp   = (const float*)d_in[10];
    float* out = (float*)d_out;

    cudaFuncSetAttribute(main_kernel, cudaFuncAttributeMaxDynamicSharedMemorySize, 98304);

    prep1_kernel<<<2048 + NB * NN + 32, 256>>>(tokens, out, states, ln_s_g, ln_s_b, Wq, ln_t_b);
    prepB_kernel<<<34, 256>>>(Wk, bk, bq);
    prepC_kernel<<<264, 256>>>(Wq, ln_t_g, temp);
    main_kernel<<<296, 256, 98304>>>();                        // profiled slot 4
    meanent_kernel<<<2048, 256>>>(out + (size_t)NTOK * TD);
    fin_kernel<<<1, 256>>>(out + (size_t)NTOK * TD + (size_t)NTOK * NN);
}

// round 14
// speedup vs baseline: 1.0624x; 1.0624x over previous
#include <cuda_runtime.h>
#include <cuda_bf16.h>
#include <cuda_fp16.h>
#include <math.h>

#define NB 4
#define NS 4096
#define NN 128
#define TD 1024
#define SD 512
#define PD 512
#define NH 4
#define HD 128
#define NTOK (NB*NS)

// ---------------- static device scratch (no runtime alloc allowed) ----------
__device__ __align__(16) __nv_bfloat16 g_Ahi[NTOK*TD];        // 32 MB
__device__ __align__(16) __nv_bfloat16 g_Alo[NTOK*TD];        // 32 MB
__device__ __align__(16) float g_sn[NB*NN*SD];                // 1 MB
__device__ __align__(16) float g_kfull[NB*NN*PD];             // 1 MB
__device__ float g_qpart[16*PD];
__device__ float g_qconst[PD];
__device__ float g_biasv[NB*PD];
__device__ __align__(16) __nv_bfloat16 g_Chi[NB*NH*TD*HD];    // 4 MB  [b][h][k][n]
__device__ __align__(16) __nv_bfloat16 g_Clo[NB*NH*TD*HD];    // 4 MB
__device__ __align__(16) __half g_w[(size_t)NB*NH*NS*NN];     // 16 MB (fp16 weights)
__device__ float g_entpart[2048];

// ---------------- PTX helpers ----------------------------------------------
__device__ __forceinline__ void ldsm4(unsigned* r, const void* p) {
    unsigned a = (unsigned)__cvta_generic_to_shared(p);
    asm volatile("ldmatrix.sync.aligned.m8n8.x4.shared.b16 {%0,%1,%2,%3}, [%4];"
                 : "=r"(r[0]), "=r"(r[1]), "=r"(r[2]), "=r"(r[3]) : "r"(a));
}
__device__ __forceinline__ void ldsm4t(unsigned* r, const void* p) {
    unsigned a = (unsigned)__cvta_generic_to_shared(p);
    asm volatile("ldmatrix.sync.aligned.m8n8.x4.trans.shared.b16 {%0,%1,%2,%3}, [%4];"
                 : "=r"(r[0]), "=r"(r[1]), "=r"(r[2]), "=r"(r[3]) : "r"(a));
}
__device__ __forceinline__ void mma_bf16(float c[4], const unsigned a[4], const unsigned b[2]) {
    asm volatile("mma.sync.aligned.m16n8k16.row.col.f32.bf16.bf16.f32 "
                 "{%0,%1,%2,%3},{%4,%5,%6,%7},{%8,%9},{%0,%1,%2,%3};"
                 : "+f"(c[0]), "+f"(c[1]), "+f"(c[2]), "+f"(c[3])
                 : "r"(a[0]), "r"(a[1]), "r"(a[2]), "r"(a[3]), "r"(b[0]), "r"(b[1]));
}
__device__ __forceinline__ void cpa16(void* s, const void* g) {
    unsigned sa = (unsigned)__cvta_generic_to_shared(s);
    asm volatile("cp.async.cg.shared.global [%0],[%1],16;" :: "r"(sa), "l"(g) : "memory");
}
#define CP_COMMIT() asm volatile("cp.async.commit_group;" ::: "memory")
#define CP_WAIT1()  asm volatile("cp.async.wait_group 1;"  ::: "memory")

// ============================================================================
// L1 prepA: state LN (512 blocks) | qconst split-K partials (32 blocks)
// ============================================================================
__global__ void prepA_kernel(const float* __restrict__ st,
                             const float* __restrict__ lnsg, const float* __restrict__ lnsb,
                             const float* __restrict__ Wq, const float* __restrict__ bt) {
    int bid = blockIdx.x, t = threadIdx.x;
    if (bid < NB * NN) {
        int row = bid;
        const float2* rp = (const float2*)(st + (size_t)row * SD);
        float2 x = rp[t];
        __shared__ float red2[8];
        __shared__ float z_mu, z_rstd;
        float p = x.x + x.y;
        #pragma unroll
        for (int o = 16; o; o >>= 1) p += __shfl_xor_sync(~0u, p, o);
        if ((t & 31) == 0) red2[t >> 5] = p;
        __syncthreads();
        if (t == 0) { float s = 0;
            #pragma unroll
            for (int i = 0; i < 8; i++) s += red2[i]; z_mu = s * (1.f / SD); }
        __syncthreads();
        float mu = z_mu;
        float d0 = x.x - mu, d1 = x.y - mu;
        p = d0*d0 + d1*d1;
        #pragma unroll
        for (int o = 16; o; o >>= 1) p += __shfl_xor_sync(~0u, p, o);
        if ((t & 31) == 0) red2[t >> 5] = p;
        __syncthreads();
        if (t == 0) { float s = 0;
            #pragma unroll
            for (int i = 0; i < 8; i++) s += red2[i]; z_rstd = rsqrtf(s * (1.f / SD) + 1e-5f); }
        __syncthreads();
        float r = z_rstd;
        int c = t * 2;
        float2 y;
        y.x = d0 * r * lnsg[c]     + lnsb[c];
        y.y = d1 * r * lnsg[c + 1] + lnsb[c + 1];
        ((float2*)(g_sn + (size_t)row * SD))[t] = y;
    } else {
        int idx = bid - NB * NN;             // 0..31
        int p = (idx & 1) * 256 + t;
        int k0 = (idx >> 1) * 64;
        float acc = 0.f;
        #pragma unroll 8
        for (int kk = 0; kk < 64; kk++) acc += bt[k0 + kk] * Wq[(size_t)(k0 + kk) * PD + p];
        g_qpart[(idx >> 1) * PD + p] = acc;
    }
}

// ============================================================================
// L2 prepB: kproj (32 blocks) | qreduce (2 blocks)
// ============================================================================
__global__ void prepB_kernel(const float* __restrict__ Wk, const float* __restrict__ bk,
                             const float* __restrict__ bq) {
    int bid = blockIdx.x, t = threadIdx.x;
    if (bid < 32) {
        int r0 = (bid & 7) * 64, p0 = (bid >> 3) * 128;
        __shared__ float sSn[64 * 33];
        __shared__ float sWk[32 * 128];
        int tr = t >> 4, tp = t & 15;
        float acc[4][8];
        #pragma unroll
        for (int i = 0; i < 4; i++)
            #pragma unroll
            for (int j = 0; j < 8; j++) acc[i][j] = 0.f;
        for (int c0 = 0; c0 < SD; c0 += 32) {
            for (int idx = t; idx < 64 * 32; idx += 256) {
                int rr = idx >> 5, cc = idx & 31;
                sSn[rr * 33 + cc] = g_sn[(size_t)(r0 + rr) * SD + c0 + cc];
            }
            for (int idx = t; idx < 32 * 128; idx += 256) {
                int cc = idx >> 7, pp = idx & 127;
                sWk[cc * 128 + pp] = Wk[(size_t)(c0 + cc) * PD + p0 + pp];
            }
            __syncthreads();
            for (int cc = 0; cc < 32; cc++) {
                float a0 = sSn[(tr*4+0)*33+cc], a1 = sSn[(tr*4+1)*33+cc];
                float a2 = sSn[(tr*4+2)*33+cc], a3 = sSn[(tr*4+3)*33+cc];
                #pragma unroll
                for (int pp = 0; pp < 8; pp++) {
                    float w = sWk[cc * 128 + tp * 8 + pp];
                    acc[0][pp] += a0 * w; acc[1][pp] += a1 * w;
                    acc[2][pp] += a2 * w; acc[3][pp] += a3 * w;
                }
            }
            __syncthreads();
        }
        #pragma unroll
        for (int rr = 0; rr < 4; rr++)
            #pragma unroll
            for (int pp = 0; pp < 8; pp++) {
                int p = p0 + tp * 8 + pp;
                g_kfull[(size_t)(r0 + tr*4 + rr) * PD + p] = acc[rr][pp] + bk[p];
            }
    } else {
        int p = (bid - 32) * 256 + t;
        float s = bq[p];
        #pragma unroll
        for (int j = 0; j < 16; j++) s += g_qpart[j * PD + p];
        g_qconst[p] = s;
    }
}

// ============================================================================
// L3 tokln: token LN -> split bf16 hi/lo + passthrough, warp-per-row
// ============================================================================
__global__ void tokln_kernel(const float* __restrict__ tok, float* __restrict__ out_tok) {
    int t = threadIdx.x, w = t >> 5, l = t & 31;
    int row = blockIdx.x * 8 + w;
    const float4* rp = (const float4*)(tok + (size_t)row * TD);
    float4* wp = (float4*)(out_tok + (size_t)row * TD);
    float4 x[8];
    #pragma unroll
    for (int j = 0; j < 8; j++) x[j] = rp[j * 32 + l];
    #pragma unroll
    for (int j = 0; j < 8; j++) wp[j * 32 + l] = x[j];   // passthrough
    float p = 0.f;
    #pragma unroll
    for (int j = 0; j < 8; j++) p += (x[j].x + x[j].y) + (x[j].z + x[j].w);
    #pragma unroll
    for (int o = 16; o; o >>= 1) p += __shfl_xor_sync(~0u, p, o);
    float mu = p * (1.f / TD);
    float v = 0.f;
    #pragma unroll
    for (int j = 0; j < 8; j++) {
        float a = x[j].x - mu, b = x[j].y - mu, c = x[j].z - mu, d = x[j].w - mu;
        v += a*a + b*b + c*c + d*d;
    }
    #pragma unroll
    for (int o = 16; o; o >>= 1) v += __shfl_xor_sync(~0u, v, o);
    float r = rsqrtf(v * (1.f / TD) + 1e-5f);
    #pragma unroll
    for (int j = 0; j < 8; j++) {
        float z0 = (x[j].x - mu) * r, z1 = (x[j].y - mu) * r;
        float z2 = (x[j].z - mu) * r, z3 = (x[j].w - mu) * r;
        union { __nv_bfloat16 b[4]; uint2 u; } hz, lz;
        hz.b[0] = __float2bfloat16(z0); lz.b[0] = __float2bfloat16(z0 - __bfloat162float(hz.b[0]));
        hz.b[1] = __float2bfloat16(z1); lz.b[1] = __float2bfloat16(z1 - __bfloat162float(hz.b[1]));
        hz.b[2] = __float2bfloat16(z2); lz.b[2] = __float2bfloat16(z2 - __bfloat162float(hz.b[2]));
        hz.b[3] = __float2bfloat16(z3); lz.b[3] = __float2bfloat16(z3 - __bfloat162float(hz.b[3]));
        int idx = (j * 32 + l) * 4;
        *reinterpret_cast<uint2*>(&g_Ahi[(size_t)row * TD + idx]) = hz.u;
        *reinterpret_cast<uint2*>(&g_Alo[(size_t)row * TD + idx]) = lz.u;
    }
}

// ============================================================================
// L4 prepC: cbuild 4kx8n register-blocked (256 blocks) | biasv (8 blocks)
// ============================================================================
__global__ void prepC_kernel(const float* __restrict__ Wq, const float* __restrict__ gt,
                             const float* __restrict__ temp) {
    int bid = blockIdx.x, t = threadIdx.x;
    if (bid < 256) {
        int kt = bid & 15, h = (bid >> 4) & 3, b = bid >> 6;
        int k0 = kt * 64;
        float invt = 1.f / fmaxf(temp[0], 0.1f);
        __shared__ float sWg[64 * 33];
        __shared__ float sKp[32 * 133];
        int tr = t >> 4, tp = t & 15;
        float acc[4][8];
        #pragma unroll
        for (int i = 0; i < 4; i++)
            #pragma unroll
            for (int j = 0; j < 8; j++) acc[i][j] = 0.f;
        int dd0 = t & 31, grp = t >> 5;
        for (int dc = 0; dc < HD; dc += 32) {
            #pragma unroll
            for (int kk = grp; kk < 64; kk += 8)
                sWg[kk * 33 + dd0] = Wq[(size_t)(k0 + kk) * PD + h * HD + dc + dd0] * gt[k0 + kk];
            #pragma unroll
            for (int n = grp; n < 128; n += 8)
                sKp[dd0 * 133 + n] = g_kfull[((size_t)(b * NN + n)) * PD + h * HD + dc + dd0] * invt;
            __syncthreads();
            #pragma unroll
            for (int dd = 0; dd < 32; dd++) {
                float a0 = sWg[(tr * 4 + 0) * 33 + dd];
                float a1 = sWg[(tr * 4 + 1) * 33 + dd];
                float a2 = sWg[(tr * 4 + 2) * 33 + dd];
                float a3 = sWg[(tr * 4 + 3) * 33 + dd];
                #pragma unroll
                for (int pp = 0; pp < 8; pp++) {
                    float w = sKp[dd * 133 + tp + 16 * pp];
                    acc[0][pp] += a0 * w; acc[1][pp] += a1 * w;
                    acc[2][pp] += a2 * w; acc[3][pp] += a3 * w;
                }
            }
            __syncthreads();
        }
        #pragma unroll
        for (int i = 0; i < 4; i++) {
            int k = k0 + tr * 4 + i;
            size_t rowb = ((size_t)(b * NH + h) * TD + k) * HD;
            #pragma unroll
            for (int pp = 0; pp < 8; pp++) {
                int n = tp + 16 * pp;
                float v = acc[i][pp];
                __nv_bfloat16 hi = __float2bfloat16(v);
                g_Chi[rowb + n] = hi;
                g_Clo[rowb + n] = __float2bfloat16(v - __bfloat162float(hi));
            }
        }
    } else {
        int gi = (bid - 256) * 256 + t;
        int b = gi >> 9, r = gi & 511;
        int h = r >> 7, n = r & 127;
        float invt = 1.f / fmaxf(temp[0], 0.1f);
        const float* kp = &g_kfull[((size_t)(b * NN + n)) * PD + h * HD];
        const float* qc = &g_qconst[h * HD];
        float acc = 0.f;
        for (int d = 0; d < HD; d++) acc += qc[d] * kp[d];
        g_biasv[b * PD + r] = acc * invt;
    }
}

// ============================================================================
// L5 main: GEMM + per-head softmax. Grid (64,4,4)=1024, 2-stage BK=64,
// 8 warps in 2m x 4n (32x32 warp tiles) -- fewer smem reads than 4m x 2n.
// ============================================================================
__global__ void __launch_bounds__(256, 2) main_kernel() {
    extern __shared__ char smem[];
    const int STG = 49152;   // per-stage: Ahi 8K | Alo 8K | Chi 16K | Clo 16K
    __shared__ float sBias[128];
    __shared__ float sMax[64][4], sSum[64][4];
    int stile = blockIdx.x, h = blockIdx.y, b = blockIdx.z;
    int t = threadIdx.x, l = t & 31, w = t >> 5;
    int wm = w >> 2, wn = w & 3;

    if (t < 128) sBias[t] = g_biasv[b * PD + h * HD + t];

    const __nv_bfloat16* gA_hi = g_Ahi + ((size_t)(b * NS + stile * 64)) * TD;
    const __nv_bfloat16* gA_lo = g_Alo + ((size_t)(b * NS + stile * 64)) * TD;
    const __nv_bfloat16* gC_hi = g_Chi + (size_t)(b * NH + h) * TD * HD;
    const __nv_bfloat16* gC_lo = g_Clo + (size_t)(b * NH + h) * TD * HD;

    auto loadStage = [&](int s, int kk) {
        char* base = smem + s * STG;
        #pragma unroll
        for (int i = 0; i < 2; i++) {
            int cid = t + i * 256, m = cid >> 3, c = cid & 7;
            int cc = c ^ (m & 7);
            cpa16(base + m * 128 + cc * 16,        gA_hi + (size_t)m * TD + kk + c * 8);
            cpa16(base + 8192 + m * 128 + cc * 16, gA_lo + (size_t)m * TD + kk + c * 8);
        }
        #pragma unroll
        for (int i = 0; i < 4; i++) {
            int cid = t + i * 256, k = cid >> 4, c = cid & 15;
            int cc = (c & 8) | ((c & 7) ^ (k & 7));
            cpa16(base + 16384 + k * 256 + cc * 16, gC_hi + (size_t)(kk + k) * HD + c * 8);
            cpa16(base + 32768 + k * 256 + cc * 16, gC_lo + (size_t)(kk + k) * HD + c * 8);
        }
    };

    // fragment indexing: warp tile rows = wm*32..+31, cols = wn*32..+31
    int mA0 = wm * 32 + (l & 15);
    int selA = l >> 4;
    int aX = mA0 & 7;
    int kb = ((l >> 3) & 1) * 8 + (l & 7);
    int cpB[2];
    #pragma unroll
    for (int p = 0; p < 2; p++) {
        int c = wn * 4 + p * 2 + (l >> 4);
        cpB[p] = (c & 8) | ((c & 7) ^ (l & 7));
    }
    int rl = l >> 2, cl = (l & 3) * 2;

    float acc[8][4];   // [r*4+q]  r in 2 (m16 halves), q in 4 (n8 tiles)
    #pragma unroll
    for (int j = 0; j < 8; j++)
        #pragma unroll
        for (int q = 0; q < 4; q++) acc[j][q] = 0.f;

    loadStage(0, 0);
    CP_COMMIT();

    for (int it = 0; it < 16; ++it) {
        if (it + 1 < 16) loadStage((it + 1) & 1, (it + 1) * 64);
        CP_COMMIT();
        CP_WAIT1();
        __syncthreads();
        char* base = smem + (it & 1) * STG;
        #pragma unroll
        for (int ks = 0; ks < 4; ++ks) {
            unsigned ahi[8], alo[8];
            int aoff = mA0 * 128 + (((ks * 2 + selA) ^ aX) << 4);
            ldsm4(&ahi[0], base + aoff);
            ldsm4(&ahi[4], base + aoff + 2048);            // +16 rows
            ldsm4(&alo[0], base + 8192 + aoff);
            ldsm4(&alo[4], base + 8192 + aoff + 2048);
            unsigned bhi[8], blo[8];
            int rowOff = (ks * 16 + kb) * 256;
            #pragma unroll
            for (int p = 0; p < 2; p++) {
                ldsm4t(&bhi[p * 4], base + 16384 + rowOff + cpB[p] * 16);
                ldsm4t(&blo[p * 4], base + 32768 + rowOff + cpB[p] * 16);
            }
            #pragma unroll
            for (int r = 0; r < 2; r++)
                #pragma unroll
                for (int q = 0; q < 4; q++) {
                    mma_bf16(acc[r * 4 + q], &ahi[r * 4], &bhi[q * 2]);
                    mma_bf16(acc[r * 4 + q], &ahi[r * 4], &blo[q * 2]);
                    mma_bf16(acc[r * 4 + q], &alo[r * 4], &bhi[q * 2]);
                }
        }
        __syncthreads();
    }

    // ---- epilogue: +bias, per-head softmax over n (4 wn warps per row) -----
    #pragma unroll
    for (int j = 0; j < 8; j++) {
        int q = j & 3;
        float b0 = sBias[wn * 32 + q * 8 + cl];
        float b1 = sBias[wn * 32 + q * 8 + cl + 1];
        acc[j][0] += b0; acc[j][1] += b1; acc[j][2] += b0; acc[j][3] += b1;
    }
    float mx[4];
    #pragma unroll
    for (int ri = 0; ri < 4; ri++) {
        int r = ri >> 1, h2 = (ri & 1) * 2;
        float m = -1e30f;
        #pragma unroll
        for (int q = 0; q < 4; q++)
            m = fmaxf(m, fmaxf(acc[r * 4 + q][h2], acc[r * 4 + q][h2 + 1]));
        m = fmaxf(m, __shfl_xor_sync(~0u, m, 1));
        m = fmaxf(m, __shfl_xor_sync(~0u, m, 2));
        mx[ri] = m;
    }
    if ((l & 3) == 0) {
        #pragma unroll
        for (int ri = 0; ri < 4; ri++) sMax[wm * 32 + ri * 8 + rl][wn] = mx[ri];
    }
    __syncthreads();
    float sm[4];
    #pragma unroll
    for (int ri = 0; ri < 4; ri++) {
        float* p = sMax[wm * 32 + ri * 8 + rl];
        mx[ri] = fmaxf(fmaxf(p[0], p[1]), fmaxf(p[2], p[3]));
        sm[ri] = 0.f;
    }
    #pragma unroll
    for (int ri = 0; ri < 4; ri++) {
        int r = ri >> 1, h2 = (ri & 1) * 2;
        #pragma unroll
        for (int q = 0; q < 4; q++) {
            acc[r * 4 + q][h2]     = __expf(acc[r * 4 + q][h2]     - mx[ri]);
            acc[r * 4 + q][h2 + 1] = __expf(acc[r * 4 + q][h2 + 1] - mx[ri]);
            sm[ri] += acc[r * 4 + q][h2] + acc[r * 4 + q][h2 + 1];
        }
        sm[ri] += __shfl_xor_sync(~0u, sm[ri], 1);
        sm[ri] += __shfl_xor_sync(~0u, sm[ri], 2);
    }
    if ((l & 3) == 0) {
        #pragma unroll
        for (int ri = 0; ri < 4; ri++) sSum[wm * 32 + ri * 8 + rl][wn] = sm[ri];
    }
    __syncthreads();
    __half* wout = g_w + ((size_t)(b * NH + h) * NS + stile * 64) * NN;
    #pragma unroll
    for (int ri = 0; ri < 4; ri++) {
        int row = wm * 32 + ri * 8 + rl;
        float* p = sSum[row];
        float inv = 1.f / ((p[0] + p[1]) + (p[2] + p[3]));
        int r = ri >> 1, h2 = (ri & 1) * 2;
        #pragma unroll
        for (int q = 0; q < 4; q++) {
            *(__half2*)(wout + (size_t)row * NN + wn * 32 + q * 8 + cl) =
                __floats2half2_rn(acc[r * 4 + q][h2] * inv, acc[r * 4 + q][h2 + 1] * inv);
        }
    }
}

// ============================================================================
// L6 meanent: head-mean + entropy partials (warp-per-row, fp16 reads)
// ============================================================================
__global__ void meanent_kernel(float* __restrict__ out_rout) {
    int t = threadIdx.x, w = t >> 5, l = t & 31;
    int row = blockIdx.x * 8 + w;
    int b = row >> 12, s = row & 4095;
    size_t hs = (size_t)NS * NN;
    size_t base = ((size_t)(b * NH) * NS + s) * NN + l * 4;
    float a0 = 0.f, a1 = 0.f, a2 = 0.f, a3 = 0.f;
    #pragma unroll
    for (int h = 0; h < NH; h++) {
        const __half2* p = (const __half2*)(g_w + base + h * hs);
        float2 x = __half22float2(p[0]);
        float2 y = __half22float2(p[1]);
        a0 += x.x; a1 += x.y; a2 += y.x; a3 += y.y;
    }
    float4 v = make_float4(a0 * 0.25f, a1 * 0.25f, a2 * 0.25f, a3 * 0.25f);
    *(float4*)(out_rout + (size_t)row * NN + l * 4) = v;
    float c = v.x * __logf(v.x + 1e-8f) + v.y * __logf(v.y + 1e-8f)
            + v.z * __logf(v.z + 1e-8f) + v.w * __logf(v.w + 1e-8f);
    #pragma unroll
    for (int o = 16; o; o >>= 1) c += __shfl_xor_sync(~0u, c, o);
    __shared__ float red[8];
    if (l == 0) red[w] = c;
    __syncthreads();
    if (t == 0) {
        float s2 = 0.f;
        #pragma unroll
        for (int i = 0; i < 8; i++) s2 += red[i];
        g_entpart[blockIdx.x] = s2;
    }
}

// ============================================================================
// L7 fin: final reduce of 2048 partials -> loss scalar
// ============================================================================
__global__ void fin_kernel(float* __restrict__ out) {
    int t = threadIdx.x;
    float s = 0.f;
    #pragma unroll
    for (int i = 0; i < 8; i++) s += g_entpart[i * 256 + t];
    #pragma unroll
    for (int o = 16; o; o >>= 1) s += __shfl_xor_sync(~0u, s, o);
    __shared__ float red[8];
    if ((t & 31) == 0) red[t >> 5] = s;
    __syncthreads();
    if (t == 0) {
        float tot = 0.f;
        #pragma unroll
        for (int i = 0; i < 8; i++) tot += red[i];
        out[0] = tot * (0.01f / (float)NTOK);
    }
}

// ---------------- launch (single stream) -------------------------------------
extern "C" void kernel_launch(void* const* d_in, const int* in_sizes, int n_in,
                              void* d_out, int out_size) {
    (void)in_sizes; (void)n_in; (void)out_size;
    const float* tokens = (const float*)d_in[0];
    const float* states = (const float*)d_in[1];
    const float* ln_t_g = (const float*)d_in[2];
    const float* ln_t_b = (const float*)d_in[3];
    const float* ln_s_g = (const float*)d_in[4];
    const float* ln_s_b = (const float*)d_in[5];
    const float* Wq     = (const float*)d_in[6];
    const float* bq     = (const float*)d_in[7];
    const float* Wk     = (const float*)d_in[8];
    const float* bk     = (const float*)d_in[9];
    const float* temp   = (const float*)d_in[10];
    float* out = (float*)d_out;

    cudaFuncSetAttribute(main_kernel, cudaFuncAttributeMaxDynamicSharedMemorySize, 98304);

    prepA_kernel<<<NB * NN + 32, 256>>>(states, ln_s_g, ln_s_b, Wq, ln_t_b);
    prepB_kernel<<<34, 256>>>(Wk, bk, bq);
    tokln_kernel<<<2048, 256>>>(tokens, out);
    prepC_kernel<<<264, 256>>>(Wq, ln_t_g, temp);
    main_kernel<<<dim3(64, 4, 4), 256, 98304>>>();
    meanent_kernel<<<2048, 256>>>(out + (size_t)NTOK * TD);
    fin_kernel<<<1, 256>>>(out + (size_t)NTOK * TD + (size_t)NTOK * NN);
}

// round 15
// speedup vs baseline: 1.0716x; 1.0086x over previous
#include <cuda_runtime.h>
#include <cuda_bf16.h>
#include <cuda_fp16.h>
#include <math.h>

#define NB 4
#define NS 4096
#define NN 128
#define TD 1024
#define SD 512
#define PD 512
#define NH 4
#define HD 128
#define NTOK (NB*NS)

// ---------------- static device scratch (no runtime alloc allowed) ----------
__device__ __align__(16) __nv_bfloat16 g_Ahi[NTOK*TD];        // 32 MB
__device__ __align__(16) __nv_bfloat16 g_Alo[NTOK*TD];        // 32 MB
__device__ __align__(16) float g_sn[NB*NN*SD];                // 1 MB
__device__ __align__(16) float g_kfull[NB*NN*PD];             // 1 MB
__device__ float g_qpart[16*PD];
__device__ float g_qconst[PD];
__device__ float g_biasv[NB*PD];
__device__ __align__(16) __nv_bfloat16 g_Chi[NB*NH*TD*HD];    // 4 MB  [b][h][k][n]
__device__ __align__(16) __nv_bfloat16 g_Clo[NB*NH*TD*HD];    // 4 MB
__device__ __align__(16) __half g_w[(size_t)NB*NH*NS*NN];     // 16 MB (fp16 weights)
__device__ float g_entpart[2048];
__device__ unsigned g_fincnt;

// ---------------- PTX helpers ----------------------------------------------
__device__ __forceinline__ void ldsm4(unsigned r[4], const void* p) {
    unsigned a = (unsigned)__cvta_generic_to_shared(p);
    asm volatile("ldmatrix.sync.aligned.m8n8.x4.shared.b16 {%0,%1,%2,%3}, [%4];"
                 : "=r"(r[0]), "=r"(r[1]), "=r"(r[2]), "=r"(r[3]) : "r"(a));
}
__device__ __forceinline__ void ldsm4t(unsigned* r, const void* p) {
    unsigned a = (unsigned)__cvta_generic_to_shared(p);
    asm volatile("ldmatrix.sync.aligned.m8n8.x4.trans.shared.b16 {%0,%1,%2,%3}, [%4];"
                 : "=r"(r[0]), "=r"(r[1]), "=r"(r[2]), "=r"(r[3]) : "r"(a));
}
__device__ __forceinline__ void mma_bf16(float c[4], const unsigned a[4], const unsigned b[2]) {
    asm volatile("mma.sync.aligned.m16n8k16.row.col.f32.bf16.bf16.f32 "
                 "{%0,%1,%2,%3},{%4,%5,%6,%7},{%8,%9},{%0,%1,%2,%3};"
                 : "+f"(c[0]), "+f"(c[1]), "+f"(c[2]), "+f"(c[3])
                 : "r"(a[0]), "r"(a[1]), "r"(a[2]), "r"(a[3]), "r"(b[0]), "r"(b[1]));
}
__device__ __forceinline__ void cpa16(void* s, const void* g) {
    unsigned sa = (unsigned)__cvta_generic_to_shared(s);
    asm volatile("cp.async.cg.shared.global [%0],[%1],16;" :: "r"(sa), "l"(g) : "memory");
}
#define CP_COMMIT() asm volatile("cp.async.commit_group;" ::: "memory")
#define CP_WAIT1()  asm volatile("cp.async.wait_group 1;"  ::: "memory")

// ============================================================================
// L1 prepA: state LN (512 blocks) | qconst split-K partials (32 blocks)
// ============================================================================
__global__ void prepA_kernel(const float* __restrict__ st,
                             const float* __restrict__ lnsg, const float* __restrict__ lnsb,
                             const float* __restrict__ Wq, const float* __restrict__ bt) {
    int bid = blockIdx.x, t = threadIdx.x;
    if (bid == 0 && t == 0) g_fincnt = 0;
    if (bid < NB * NN) {
        int row = bid;
        const float2* rp = (const float2*)(st + (size_t)row * SD);
        float2 x = rp[t];
        __shared__ float red2[8];
        __shared__ float z_mu, z_rstd;
        float p = x.x + x.y;
        #pragma unroll
        for (int o = 16; o; o >>= 1) p += __shfl_xor_sync(~0u, p, o);
        if ((t & 31) == 0) red2[t >> 5] = p;
        __syncthreads();
        if (t == 0) { float s = 0;
            #pragma unroll
            for (int i = 0; i < 8; i++) s += red2[i]; z_mu = s * (1.f / SD); }
        __syncthreads();
        float mu = z_mu;
        float d0 = x.x - mu, d1 = x.y - mu;
        p = d0*d0 + d1*d1;
        #pragma unroll
        for (int o = 16; o; o >>= 1) p += __shfl_xor_sync(~0u, p, o);
        if ((t & 31) == 0) red2[t >> 5] = p;
        __syncthreads();
        if (t == 0) { float s = 0;
            #pragma unroll
            for (int i = 0; i < 8; i++) s += red2[i]; z_rstd = rsqrtf(s * (1.f / SD) + 1e-5f); }
        __syncthreads();
        float r = z_rstd;
        int c = t * 2;
        float2 y;
        y.x = d0 * r * lnsg[c]     + lnsb[c];
        y.y = d1 * r * lnsg[c + 1] + lnsb[c + 1];
        ((float2*)(g_sn + (size_t)row * SD))[t] = y;
    } else {
        int idx = bid - NB * NN;             // 0..31
        int p = (idx & 1) * 256 + t;
        int k0 = (idx >> 1) * 64;
        float acc = 0.f;
        #pragma unroll 8
        for (int kk = 0; kk < 64; kk++) acc += bt[k0 + kk] * Wq[(size_t)(k0 + kk) * PD + p];
        g_qpart[(idx >> 1) * PD + p] = acc;
    }
}

// ============================================================================
// L2 prepB: kproj (32 blocks) | qreduce (2 blocks)
// ============================================================================
__global__ void prepB_kernel(const float* __restrict__ Wk, const float* __restrict__ bk,
                             const float* __restrict__ bq) {
    int bid = blockIdx.x, t = threadIdx.x;
    if (bid < 32) {
        int r0 = (bid & 7) * 64, p0 = (bid >> 3) * 128;
        __shared__ float sSn[64 * 33];
        __shared__ float sWk[32 * 128];
        int tr = t >> 4, tp = t & 15;
        float acc[4][8];
        #pragma unroll
        for (int i = 0; i < 4; i++)
            #pragma unroll
            for (int j = 0; j < 8; j++) acc[i][j] = 0.f;
        for (int c0 = 0; c0 < SD; c0 += 32) {
            for (int idx = t; idx < 64 * 32; idx += 256) {
                int rr = idx >> 5, cc = idx & 31;
                sSn[rr * 33 + cc] = g_sn[(size_t)(r0 + rr) * SD + c0 + cc];
            }
            for (int idx = t; idx < 32 * 128; idx += 256) {
                int cc = idx >> 7, pp = idx & 127;
                sWk[cc * 128 + pp] = Wk[(size_t)(c0 + cc) * PD + p0 + pp];
            }
            __syncthreads();
            for (int cc = 0; cc < 32; cc++) {
                float a0 = sSn[(tr*4+0)*33+cc], a1 = sSn[(tr*4+1)*33+cc];
                float a2 = sSn[(tr*4+2)*33+cc], a3 = sSn[(tr*4+3)*33+cc];
                #pragma unroll
                for (int pp = 0; pp < 8; pp++) {
                    float w = sWk[cc * 128 + tp * 8 + pp];
                    acc[0][pp] += a0 * w; acc[1][pp] += a1 * w;
                    acc[2][pp] += a2 * w; acc[3][pp] += a3 * w;
                }
            }
            __syncthreads();
        }
        #pragma unroll
        for (int rr = 0; rr < 4; rr++)
            #pragma unroll
            for (int pp = 0; pp < 8; pp++) {
                int p = p0 + tp * 8 + pp;
                g_kfull[(size_t)(r0 + tr*4 + rr) * PD + p] = acc[rr][pp] + bk[p];
            }
    } else {
        int p = (bid - 32) * 256 + t;
        float s = bq[p];
        #pragma unroll
        for (int j = 0; j < 16; j++) s += g_qpart[j * PD + p];
        g_qconst[p] = s;
    }
}

// ============================================================================
// L3 tokln: token LN -> split bf16 hi/lo + passthrough, warp-per-row
// ============================================================================
__global__ void tokln_kernel(const float* __restrict__ tok, float* __restrict__ out_tok) {
    int t = threadIdx.x, w = t >> 5, l = t & 31;
    int row = blockIdx.x * 8 + w;
    const float4* rp = (const float4*)(tok + (size_t)row * TD);
    float4* wp = (float4*)(out_tok + (size_t)row * TD);
    float4 x[8];
    #pragma unroll
    for (int j = 0; j < 8; j++) x[j] = rp[j * 32 + l];
    #pragma unroll
    for (int j = 0; j < 8; j++) wp[j * 32 + l] = x[j];   // passthrough
    float p = 0.f;
    #pragma unroll
    for (int j = 0; j < 8; j++) p += (x[j].x + x[j].y) + (x[j].z + x[j].w);
    #pragma unroll
    for (int o = 16; o; o >>= 1) p += __shfl_xor_sync(~0u, p, o);
    float mu = p * (1.f / TD);
    float v = 0.f;
    #pragma unroll
    for (int j = 0; j < 8; j++) {
        float a = x[j].x - mu, b = x[j].y - mu, c = x[j].z - mu, d = x[j].w - mu;
        v += a*a + b*b + c*c + d*d;
    }
    #pragma unroll
    for (int o = 16; o; o >>= 1) v += __shfl_xor_sync(~0u, v, o);
    float r = rsqrtf(v * (1.f / TD) + 1e-5f);
    #pragma unroll
    for (int j = 0; j < 8; j++) {
        float z0 = (x[j].x - mu) * r, z1 = (x[j].y - mu) * r;
        float z2 = (x[j].z - mu) * r, z3 = (x[j].w - mu) * r;
        union { __nv_bfloat16 b[4]; uint2 u; } hz, lz;
        hz.b[0] = __float2bfloat16(z0); lz.b[0] = __float2bfloat16(z0 - __bfloat162float(hz.b[0]));
        hz.b[1] = __float2bfloat16(z1); lz.b[1] = __float2bfloat16(z1 - __bfloat162float(hz.b[1]));
        hz.b[2] = __float2bfloat16(z2); lz.b[2] = __float2bfloat16(z2 - __bfloat162float(hz.b[2]));
        hz.b[3] = __float2bfloat16(z3); lz.b[3] = __float2bfloat16(z3 - __bfloat162float(hz.b[3]));
        int idx = (j * 32 + l) * 4;
        *reinterpret_cast<uint2*>(&g_Ahi[(size_t)row * TD + idx]) = hz.u;
        *reinterpret_cast<uint2*>(&g_Alo[(size_t)row * TD + idx]) = lz.u;
    }
}

// ============================================================================
// L4 prepC (PROFILED): cbuild, 32 k-tiles (512 blocks, 32k x 128n, acc 2x8)
// | biasv (8 blocks)
// ============================================================================
__global__ void prepC_kernel(const float* __restrict__ Wq, const float* __restrict__ gt,
                             const float* __restrict__ temp) {
    int bid = blockIdx.x, t = threadIdx.x;
    if (bid < 512) {
        int kt = bid & 31, h = (bid >> 5) & 3, b = bid >> 7;
        int k0 = kt * 32;
        float invt = 1.f / fmaxf(temp[0], 0.1f);
        __shared__ float sWg[32 * 33];    // [k][dd] pad 33
        __shared__ float sKp[32 * 133];   // [dd][n] pad 133
        int tr = t >> 4, tp = t & 15;     // tr 0..15 -> 2 k rows each
        float acc[2][8];
        #pragma unroll
        for (int i = 0; i < 2; i++)
            #pragma unroll
            for (int j = 0; j < 8; j++) acc[i][j] = 0.f;
        int dd0 = t & 31, grp = t >> 5;
        for (int dc = 0; dc < HD; dc += 32) {
            #pragma unroll
            for (int kk = grp; kk < 32; kk += 8)
                sWg[kk * 33 + dd0] = Wq[(size_t)(k0 + kk) * PD + h * HD + dc + dd0] * gt[k0 + kk];
            #pragma unroll
            for (int n = grp; n < 128; n += 8)
                sKp[dd0 * 133 + n] = g_kfull[((size_t)(b * NN + n)) * PD + h * HD + dc + dd0] * invt;
            __syncthreads();
            #pragma unroll
            for (int dd = 0; dd < 32; dd++) {
                float a0 = sWg[(tr * 2 + 0) * 33 + dd];
                float a1 = sWg[(tr * 2 + 1) * 33 + dd];
                #pragma unroll
                for (int pp = 0; pp < 8; pp++) {
                    float w = sKp[dd * 133 + tp + 16 * pp];
                    acc[0][pp] += a0 * w;
                    acc[1][pp] += a1 * w;
                }
            }
            __syncthreads();
        }
        #pragma unroll
        for (int i = 0; i < 2; i++) {
            int k = k0 + tr * 2 + i;
            size_t rowb = ((size_t)(b * NH + h) * TD + k) * HD;
            #pragma unroll
            for (int pp = 0; pp < 8; pp++) {
                int n = tp + 16 * pp;
                float v = acc[i][pp];
                __nv_bfloat16 hi = __float2bfloat16(v);
                g_Chi[rowb + n] = hi;
                g_Clo[rowb + n] = __float2bfloat16(v - __bfloat162float(hi));
            }
        }
    } else {
        int gi = (bid - 512) * 256 + t;   // 0..2047
        int b = gi >> 9, r = gi & 511;
        int h = r >> 7, n = r & 127;
        float invt = 1.f / fmaxf(temp[0], 0.1f);
        const float* kp = &g_kfull[((size_t)(b * NN + n)) * PD + h * HD];
        const float* qc = &g_qconst[h * HD];
        float acc = 0.f;
        for (int d = 0; d < HD; d++) acc += qc[d] * kp[d];
        g_biasv[b * PD + r] = acc * invt;
    }
}

// ============================================================================
// L5 main: GEMM + per-head softmax (R12 exact: BK=64, 2-stage, 4m x 2n)
// grid (stile=64, h=4, b=4), block 256 (8 warps), BM=64 BN=128
// ============================================================================
__global__ void __launch_bounds__(256, 2) main_kernel() {
    extern __shared__ char smem[];
    int stile = blockIdx.x, h = blockIdx.y, b = blockIdx.z;
    int t = threadIdx.x, l = t & 31, w = t >> 5;
    int wm = w >> 1, wn = w & 1;
    const int STG = 49152;   // per-stage: Ahi 8K | Alo 8K | Chi 16K | Clo 16K
    __shared__ float sBias[128];
    __shared__ float sMax[64][2], sSum[64][2];
    if (t < 128) sBias[t] = g_biasv[b * PD + h * HD + t];

    const __nv_bfloat16* gA_hi = g_Ahi + ((size_t)(b * NS + stile * 64)) * TD;
    const __nv_bfloat16* gA_lo = g_Alo + ((size_t)(b * NS + stile * 64)) * TD;
    const __nv_bfloat16* gC_hi = g_Chi + (size_t)(b * NH + h) * TD * HD;
    const __nv_bfloat16* gC_lo = g_Clo + (size_t)(b * NH + h) * TD * HD;

    auto loadStage = [&](int s, int kk) {
        char* base = smem + s * STG;
        #pragma unroll
        for (int i = 0; i < 2; i++) {
            int cid = t + i * 256, m = cid >> 3, c = cid & 7;
            int cc = c ^ (m & 7);
            cpa16(base + m * 128 + cc * 16,        gA_hi + (size_t)m * TD + kk + c * 8);
            cpa16(base + 8192 + m * 128 + cc * 16, gA_lo + (size_t)m * TD + kk + c * 8);
        }
        #pragma unroll
        for (int i = 0; i < 4; i++) {
            int cid = t + i * 256, k = cid >> 4, c = cid & 15;
            int cc = (c & 8) | ((c & 7) ^ (k & 7));
            cpa16(base + 16384 + k * 256 + cc * 16, gC_hi + (size_t)(kk + k) * HD + c * 8);
            cpa16(base + 32768 + k * 256 + cc * 16, gC_lo + (size_t)(kk + k) * HD + c * 8);
        }
    };

    float acc[8][4];
    #pragma unroll
    for (int j = 0; j < 8; j++)
        #pragma unroll
        for (int q = 0; q < 4; q++) acc[j][q] = 0.f;

    int mA = wm * 16 + (l & 15);
    int selA = l >> 4;
    int aRowOff = mA * 128, aX = mA & 7;
    int kb = ((l >> 3) & 1) * 8 + (l & 7);
    int cpB[4];
    #pragma unroll
    for (int q = 0; q < 4; q++) {
        int c = wn * 8 + q * 2 + (l >> 4);
        cpB[q] = (c & 8) | ((c & 7) ^ (l & 7));
    }

    loadStage(0, 0);
    CP_COMMIT();

    for (int it = 0; it < 16; ++it) {
        if (it + 1 < 16) loadStage((it + 1) & 1, (it + 1) * 64);
        CP_COMMIT();
        CP_WAIT1();
        __syncthreads();
        char* base = smem + (it & 1) * STG;
        #pragma unroll
        for (int ks = 0; ks < 4; ++ks) {
            unsigned ahi[4], alo[4];
            int aoff = aRowOff + (((ks * 2 + selA) ^ aX) << 4);
            ldsm4(ahi, base + aoff);
            ldsm4(alo, base + 8192 + aoff);
            unsigned bhi[16], blo[16];
            #pragma unroll
            for (int q = 0; q < 4; q++) {
                int off = (ks * 16 + kb) * 256 + cpB[q] * 16;
                ldsm4t(&bhi[q * 4], base + 16384 + off);
                ldsm4t(&blo[q * 4], base + 32768 + off);
            }
            #pragma unroll
            for (int j = 0; j < 8; j++) {
                mma_bf16(acc[j], ahi, &bhi[j * 2]);
                mma_bf16(acc[j], ahi, &blo[j * 2]);
                mma_bf16(acc[j], alo, &bhi[j * 2]);
            }
        }
        __syncthreads();
    }

    // ---- epilogue: +bias, per-head softmax over n (BN=128 = all states) ----
    int r0 = wm * 16 + (l >> 2);
    int cb = wn * 64 + (l & 3) * 2;
    #pragma unroll
    for (int j = 0; j < 8; j++) {
        float b0 = sBias[cb + j * 8], b1 = sBias[cb + j * 8 + 1];
        acc[j][0] += b0; acc[j][1] += b1; acc[j][2] += b0; acc[j][3] += b1;
    }
    float mx0 = -1e30f, mx8 = -1e30f;
    #pragma unroll
    for (int j = 0; j < 8; j++) {
        mx0 = fmaxf(mx0, fmaxf(acc[j][0], acc[j][1]));
        mx8 = fmaxf(mx8, fmaxf(acc[j][2], acc[j][3]));
    }
    mx0 = fmaxf(mx0, __shfl_xor_sync(~0u, mx0, 1));
    mx0 = fmaxf(mx0, __shfl_xor_sync(~0u, mx0, 2));
    mx8 = fmaxf(mx8, __shfl_xor_sync(~0u, mx8, 1));
    mx8 = fmaxf(mx8, __shfl_xor_sync(~0u, mx8, 2));
    if ((l & 3) == 0) { sMax[r0][wn] = mx0; sMax[r0 + 8][wn] = mx8; }
    __syncthreads();
    float M0 = fmaxf(sMax[r0][0], sMax[r0][1]);
    float M8 = fmaxf(sMax[r0 + 8][0], sMax[r0 + 8][1]);
    float s0 = 0.f, s8 = 0.f;
    #pragma unroll
    for (int j = 0; j < 8; j++) {
        acc[j][0] = __expf(acc[j][0] - M0); s0 += acc[j][0];
        acc[j][1] = __expf(acc[j][1] - M0); s0 += acc[j][1];
        acc[j][2] = __expf(acc[j][2] - M8); s8 += acc[j][2];
        acc[j][3] = __expf(acc[j][3] - M8); s8 += acc[j][3];
    }
    s0 += __shfl_xor_sync(~0u, s0, 1); s0 += __shfl_xor_sync(~0u, s0, 2);
    s8 += __shfl_xor_sync(~0u, s8, 1); s8 += __shfl_xor_sync(~0u, s8, 2);
    if ((l & 3) == 0) { sSum[r0][wn] = s0; sSum[r0 + 8][wn] = s8; }
    __syncthreads();
    float inv0 = 1.f / (sSum[r0][0] + sSum[r0][1]);
    float inv8 = 1.f / (sSum[r0 + 8][0] + sSum[r0 + 8][1]);
    __half* wout = g_w + ((size_t)(b * NH + h) * NS + stile * 64) * NN;
    #pragma unroll
    for (int j = 0; j < 8; j++) {
        *(__half2*)(wout + (size_t)r0 * NN + cb + j * 8) =
            __floats2half2_rn(acc[j][0] * inv0, acc[j][1] * inv0);
        *(__half2*)(wout + (size_t)(r0 + 8) * NN + cb + j * 8) =
            __floats2half2_rn(acc[j][2] * inv8, acc[j][3] * inv8);
    }
}

// ============================================================================
// L6 meanent: head-mean + entropy; LAST block reduces all partials (no fin)
// ============================================================================
__global__ void meanent_kernel(float* __restrict__ out_rout, float* __restrict__ out_loss) {
    int t = threadIdx.x, w = t >> 5, l = t & 31;
    int row = blockIdx.x * 8 + w;
    int b = row >> 12, s = row & 4095;
    size_t hs = (size_t)NS * NN;
    size_t base = ((size_t)(b * NH) * NS + s) * NN + l * 4;
    float a0 = 0.f, a1 = 0.f, a2 = 0.f, a3 = 0.f;
    #pragma unroll
    for (int h = 0; h < NH; h++) {
        const __half2* p = (const __half2*)(g_w + base + h * hs);
        float2 x = __half22float2(p[0]);
        float2 y = __half22float2(p[1]);
        a0 += x.x; a1 += x.y; a2 += y.x; a3 += y.y;
    }
    float4 v = make_float4(a0 * 0.25f, a1 * 0.25f, a2 * 0.25f, a3 * 0.25f);
    *(float4*)(out_rout + (size_t)row * NN + l * 4) = v;
    float c = v.x * __logf(v.x + 1e-8f) + v.y * __logf(v.y + 1e-8f)
            + v.z * __logf(v.z + 1e-8f) + v.w * __logf(v.w + 1e-8f);
    #pragma unroll
    for (int o = 16; o; o >>= 1) c += __shfl_xor_sync(~0u, c, o);
    __shared__ float red[8];
    __shared__ int isLast;
    if (l == 0) red[w] = c;
    __syncthreads();
    if (t == 0) {
        float s2 = 0.f;
        #pragma unroll
        for (int i = 0; i < 8; i++) s2 += red[i];
        g_entpart[blockIdx.x] = s2;
        __threadfence();
        unsigned old = atomicAdd(&g_fincnt, 1u);
        isLast = (old == 2047u);
    }
    __syncthreads();
    if (isLast) {
        float s2 = 0.f;
        #pragma unroll
        for (int i = 0; i < 8; i++) s2 += g_entpart[i * 256 + t];
        #pragma unroll
        for (int o = 16; o; o >>= 1) s2 += __shfl_xor_sync(~0u, s2, o);
        if (l == 0) red[w] = s2;
        __syncthreads();
        if (t == 0) {
            float tot = 0.f;
            #pragma unroll
            for (int i = 0; i < 8; i++) tot += red[i];
            out_loss[0] = tot * (0.01f / (float)NTOK);
        }
    }
}

// ---------------- launch (single stream) -------------------------------------
extern "C" void kernel_launch(void* const* d_in, const int* in_sizes, int n_in,
                              void* d_out, int out_size) {
    (void)in_sizes; (void)n_in; (void)out_size;
    const float* tokens = (const float*)d_in[0];
    const float* states = (const float*)d_in[1];
    const float* ln_t_g = (const float*)d_in[2];
    const float* ln_t_b = (const float*)d_in[3];
    const float* ln_s_g = (const float*)d_in[4];
    const float* ln_s_b = (const float*)d_in[5];
    const float* Wq     = (const float*)d_in[6];
    const float* bq     = (const float*)d_in[7];
    const float* Wk     = (const float*)d_in[8];
    const float* bk     = (const float*)d_in[9];
    const float* temp   = (const float*)d_in[10];
    float* out = (float*)d_out;

    cudaFuncSetAttribute(main_kernel, cudaFuncAttributeMaxDynamicSharedMemorySize, 98304);

    prepA_kernel<<<NB * NN + 32, 256>>>(states, ln_s_g, ln_s_b, Wq, ln_t_b);
    prepB_kernel<<<34, 256>>>(Wk, bk, bq);
    tokln_kernel<<<2048, 256>>>(tokens, out);
    prepC_kernel<<<520, 256>>>(Wq, ln_t_g, temp);                     // profiled slot 4
    main_kernel<<<dim3(64, 4, 4), 256, 98304>>>();
    meanent_kernel<<<2048, 256>>>(out + (size_t)NTOK * TD,
                                  out + (size_t)NTOK * TD + (size_t)NTOK * NN);
}

// round 16
// speedup vs baseline: 1.2437x; 1.1606x over previous
#include <cuda_runtime.h>
#include <cuda_bf16.h>
#include <cuda_fp16.h>
#include <math.h>

#define NB 4
#define NS 4096
#define NN 128
#define TD 1024
#define SD 512
#define PD 512
#define NH 4
#define HD 128
#define NTOK (NB*NS)

// ---------------- static device scratch (no runtime alloc allowed) ----------
__device__ __align__(16) __half g_Ahi[NTOK*TD];               // 32 MB (fp16 hi)
__device__ __align__(16) __half g_Alo[NTOK*TD];               // 32 MB (fp16 lo)
__device__ __align__(16) float g_sn[NB*NN*SD];                // 1 MB
__device__ __align__(16) float g_kfull[NB*NN*PD];             // 1 MB
__device__ float g_qpart[16*PD];
__device__ float g_qconst[PD];
__device__ float g_biasv[NB*PD];
__device__ __align__(16) __half g_Cf[NB*NH*TD*HD];            // 4 MB [b][h][k][n] fp16
__device__ __align__(16) __half g_w[(size_t)NB*NH*NS*NN];     // 16 MB (fp16 weights)
__device__ float g_entpart[2048];
__device__ unsigned g_fincnt;

// ---------------- PTX helpers ----------------------------------------------
__device__ __forceinline__ void ldsm4(unsigned r[4], const void* p) {
    unsigned a = (unsigned)__cvta_generic_to_shared(p);
    asm volatile("ldmatrix.sync.aligned.m8n8.x4.shared.b16 {%0,%1,%2,%3}, [%4];"
                 : "=r"(r[0]), "=r"(r[1]), "=r"(r[2]), "=r"(r[3]) : "r"(a));
}
__device__ __forceinline__ void ldsm4t(unsigned* r, const void* p) {
    unsigned a = (unsigned)__cvta_generic_to_shared(p);
    asm volatile("ldmatrix.sync.aligned.m8n8.x4.trans.shared.b16 {%0,%1,%2,%3}, [%4];"
                 : "=r"(r[0]), "=r"(r[1]), "=r"(r[2]), "=r"(r[3]) : "r"(a));
}
__device__ __forceinline__ void mma_f16(float c[4], const unsigned a[4], const unsigned b[2]) {
    asm volatile("mma.sync.aligned.m16n8k16.row.col.f32.f16.f16.f32 "
                 "{%0,%1,%2,%3},{%4,%5,%6,%7},{%8,%9},{%0,%1,%2,%3};"
                 : "+f"(c[0]), "+f"(c[1]), "+f"(c[2]), "+f"(c[3])
                 : "r"(a[0]), "r"(a[1]), "r"(a[2]), "r"(a[3]), "r"(b[0]), "r"(b[1]));
}
__device__ __forceinline__ void cpa16(void* s, const void* g) {
    unsigned sa = (unsigned)__cvta_generic_to_shared(s);
    asm volatile("cp.async.cg.shared.global [%0],[%1],16;" :: "r"(sa), "l"(g) : "memory");
}
#define CP_COMMIT() asm volatile("cp.async.commit_group;" ::: "memory")
#define CP_WAIT1()  asm volatile("cp.async.wait_group 1;"  ::: "memory")

// ============================================================================
// L1 prepA: state LN (512 blocks) | qconst split-K partials (32 blocks)
// ============================================================================
__global__ void prepA_kernel(const float* __restrict__ st,
                             const float* __restrict__ lnsg, const float* __restrict__ lnsb,
                             const float* __restrict__ Wq, const float* __restrict__ bt) {
    int bid = blockIdx.x, t = threadIdx.x;
    if (bid == 0 && t == 0) g_fincnt = 0;
    if (bid < NB * NN) {
        int row = bid;
        const float2* rp = (const float2*)(st + (size_t)row * SD);
        float2 x = rp[t];
        __shared__ float red2[8];
        __shared__ float z_mu, z_rstd;
        float p = x.x + x.y;
        #pragma unroll
        for (int o = 16; o; o >>= 1) p += __shfl_xor_sync(~0u, p, o);
        if ((t & 31) == 0) red2[t >> 5] = p;
        __syncthreads();
        if (t == 0) { float s = 0;
            #pragma unroll
            for (int i = 0; i < 8; i++) s += red2[i]; z_mu = s * (1.f / SD); }
        __syncthreads();
        float mu = z_mu;
        float d0 = x.x - mu, d1 = x.y - mu;
        p = d0*d0 + d1*d1;
        #pragma unroll
        for (int o = 16; o; o >>= 1) p += __shfl_xor_sync(~0u, p, o);
        if ((t & 31) == 0) red2[t >> 5] = p;
        __syncthreads();
        if (t == 0) { float s = 0;
            #pragma unroll
            for (int i = 0; i < 8; i++) s += red2[i]; z_rstd = rsqrtf(s * (1.f / SD) + 1e-5f); }
        __syncthreads();
        float r = z_rstd;
        int c = t * 2;
        float2 y;
        y.x = d0 * r * lnsg[c]     + lnsb[c];
        y.y = d1 * r * lnsg[c + 1] + lnsb[c + 1];
        ((float2*)(g_sn + (size_t)row * SD))[t] = y;
    } else {
        int idx = bid - NB * NN;             // 0..31
        int p = (idx & 1) * 256 + t;
        int k0 = (idx >> 1) * 64;
        float acc = 0.f;
        #pragma unroll 8
        for (int kk = 0; kk < 64; kk++) acc += bt[k0 + kk] * Wq[(size_t)(k0 + kk) * PD + p];
        g_qpart[(idx >> 1) * PD + p] = acc;
    }
}

// ============================================================================
// L2 prepB: kproj (32 blocks) | qreduce (2 blocks)
// ============================================================================
__global__ void prepB_kernel(const float* __restrict__ Wk, const float* __restrict__ bk,
                             const float* __restrict__ bq) {
    int bid = blockIdx.x, t = threadIdx.x;
    if (bid < 32) {
        int r0 = (bid & 7) * 64, p0 = (bid >> 3) * 128;
        __shared__ float sSn[64 * 33];
        __shared__ float sWk[32 * 128];
        int tr = t >> 4, tp = t & 15;
        float acc[4][8];
        #pragma unroll
        for (int i = 0; i < 4; i++)
            #pragma unroll
            for (int j = 0; j < 8; j++) acc[i][j] = 0.f;
        for (int c0 = 0; c0 < SD; c0 += 32) {
            for (int idx = t; idx < 64 * 32; idx += 256) {
                int rr = idx >> 5, cc = idx & 31;
                sSn[rr * 33 + cc] = g_sn[(size_t)(r0 + rr) * SD + c0 + cc];
            }
            for (int idx = t; idx < 32 * 128; idx += 256) {
                int cc = idx >> 7, pp = idx & 127;
                sWk[cc * 128 + pp] = Wk[(size_t)(c0 + cc) * PD + p0 + pp];
            }
            __syncthreads();
            for (int cc = 0; cc < 32; cc++) {
                float a0 = sSn[(tr*4+0)*33+cc], a1 = sSn[(tr*4+1)*33+cc];
                float a2 = sSn[(tr*4+2)*33+cc], a3 = sSn[(tr*4+3)*33+cc];
                #pragma unroll
                for (int pp = 0; pp < 8; pp++) {
                    float w = sWk[cc * 128 + tp * 8 + pp];
                    acc[0][pp] += a0 * w; acc[1][pp] += a1 * w;
                    acc[2][pp] += a2 * w; acc[3][pp] += a3 * w;
                }
            }
            __syncthreads();
        }
        #pragma unroll
        for (int rr = 0; rr < 4; rr++)
            #pragma unroll
            for (int pp = 0; pp < 8; pp++) {
                int p = p0 + tp * 8 + pp;
                g_kfull[(size_t)(r0 + tr*4 + rr) * PD + p] = acc[rr][pp] + bk[p];
            }
    } else {
        int p = (bid - 32) * 256 + t;
        float s = bq[p];
        #pragma unroll
        for (int j = 0; j < 16; j++) s += g_qpart[j * PD + p];
        g_qconst[p] = s;
    }
}

// ============================================================================
// L3 tokln: token LN -> fp16 hi/lo split + passthrough, warp-per-row
// ============================================================================
__global__ void tokln_kernel(const float* __restrict__ tok, float* __restrict__ out_tok) {
    int t = threadIdx.x, w = t >> 5, l = t & 31;
    int row = blockIdx.x * 8 + w;
    const float4* rp = (const float4*)(tok + (size_t)row * TD);
    float4* wp = (float4*)(out_tok + (size_t)row * TD);
    float4 x[8];
    #pragma unroll
    for (int j = 0; j < 8; j++) x[j] = rp[j * 32 + l];
    #pragma unroll
    for (int j = 0; j < 8; j++) wp[j * 32 + l] = x[j];   // passthrough
    float p = 0.f;
    #pragma unroll
    for (int j = 0; j < 8; j++) p += (x[j].x + x[j].y) + (x[j].z + x[j].w);
    #pragma unroll
    for (int o = 16; o; o >>= 1) p += __shfl_xor_sync(~0u, p, o);
    float mu = p * (1.f / TD);
    float v = 0.f;
    #pragma unroll
    for (int j = 0; j < 8; j++) {
        float a = x[j].x - mu, b = x[j].y - mu, c = x[j].z - mu, d = x[j].w - mu;
        v += a*a + b*b + c*c + d*d;
    }
    #pragma unroll
    for (int o = 16; o; o >>= 1) v += __shfl_xor_sync(~0u, v, o);
    float r = rsqrtf(v * (1.f / TD) + 1e-5f);
    #pragma unroll
    for (int j = 0; j < 8; j++) {
        float z0 = (x[j].x - mu) * r, z1 = (x[j].y - mu) * r;
        float z2 = (x[j].z - mu) * r, z3 = (x[j].w - mu) * r;
        union { __half h[4]; uint2 u; } hz, lz;
        hz.h[0] = __float2half_rn(z0); lz.h[0] = __float2half_rn(z0 - __half2float(hz.h[0]));
        hz.h[1] = __float2half_rn(z1); lz.h[1] = __float2half_rn(z1 - __half2float(hz.h[1]));
        hz.h[2] = __float2half_rn(z2); lz.h[2] = __float2half_rn(z2 - __half2float(hz.h[2]));
        hz.h[3] = __float2half_rn(z3); lz.h[3] = __float2half_rn(z3 - __half2float(hz.h[3]));
        int idx = (j * 32 + l) * 4;
        *reinterpret_cast<uint2*>(&g_Ahi[(size_t)row * TD + idx]) = hz.u;
        *reinterpret_cast<uint2*>(&g_Alo[(size_t)row * TD + idx]) = lz.u;
    }
}

// ============================================================================
// L4 prepC: cbuild 4kx8n register-blocked (256 blocks), single fp16 C out
// | biasv (8 blocks)
// ============================================================================
__global__ void prepC_kernel(const float* __restrict__ Wq, const float* __restrict__ gt,
                             const float* __restrict__ temp) {
    int bid = blockIdx.x, t = threadIdx.x;
    if (bid < 256) {
        int kt = bid & 15, h = (bid >> 4) & 3, b = bid >> 6;
        int k0 = kt * 64;
        float invt = 1.f / fmaxf(temp[0], 0.1f);
        __shared__ float sWg[64 * 33];
        __shared__ float sKp[32 * 133];
        int tr = t >> 4, tp = t & 15;
        float acc[4][8];
        #pragma unroll
        for (int i = 0; i < 4; i++)
            #pragma unroll
            for (int j = 0; j < 8; j++) acc[i][j] = 0.f;
        int dd0 = t & 31, grp = t >> 5;
        for (int dc = 0; dc < HD; dc += 32) {
            #pragma unroll
            for (int kk = grp; kk < 64; kk += 8)
                sWg[kk * 33 + dd0] = Wq[(size_t)(k0 + kk) * PD + h * HD + dc + dd0] * gt[k0 + kk];
            #pragma unroll
            for (int n = grp; n < 128; n += 8)
                sKp[dd0 * 133 + n] = g_kfull[((size_t)(b * NN + n)) * PD + h * HD + dc + dd0] * invt;
            __syncthreads();
            #pragma unroll
            for (int dd = 0; dd < 32; dd++) {
                float a0 = sWg[(tr * 4 + 0) * 33 + dd];
                float a1 = sWg[(tr * 4 + 1) * 33 + dd];
                float a2 = sWg[(tr * 4 + 2) * 33 + dd];
                float a3 = sWg[(tr * 4 + 3) * 33 + dd];
                #pragma unroll
                for (int pp = 0; pp < 8; pp++) {
                    float w = sKp[dd * 133 + tp + 16 * pp];
                    acc[0][pp] += a0 * w; acc[1][pp] += a1 * w;
                    acc[2][pp] += a2 * w; acc[3][pp] += a3 * w;
                }
            }
            __syncthreads();
        }
        #pragma unroll
        for (int i = 0; i < 4; i++) {
            int k = k0 + tr * 4 + i;
            size_t rowb = ((size_t)(b * NH + h) * TD + k) * HD;
            #pragma unroll
            for (int pp = 0; pp < 8; pp++) {
                int n = tp + 16 * pp;
                g_Cf[rowb + n] = __float2half_rn(acc[i][pp]);
            }
        }
    } else {
        int gi = (bid - 256) * 256 + t;
        int b = gi >> 9, r = gi & 511;
        int h = r >> 7, n = r & 127;
        float invt = 1.f / fmaxf(temp[0], 0.1f);
        const float* kp = &g_kfull[((size_t)(b * NN + n)) * PD + h * HD];
        const float* qc = &g_qconst[h * HD];
        float acc = 0.f;
        for (int d = 0; d < HD; d++) acc += qc[d] * kp[d];
        g_biasv[b * PD + r] = acc * invt;
    }
}

// ============================================================================
// L5 main: fp16 A-split 2-stream GEMM + per-head softmax
// grid (stile=64, h=4, b=4), block 256 (8 warps: 4m x 2n), BM=64 BN=128 BK=64
// stage 32KB: Ahi 8K | Alo 8K | Cf 16K;  2 stages = 64KB
// ============================================================================
#define MSTG 32768
__global__ void __launch_bounds__(256, 2) main_kernel() {
    extern __shared__ char smem[];
    int stile = blockIdx.x, h = blockIdx.y, b = blockIdx.z;
    int t = threadIdx.x, l = t & 31, w = t >> 5;
    int wm = w >> 1, wn = w & 1;
    __shared__ float sBias[128];
    __shared__ float sMax[64][2], sSum[64][2];
    if (t < 128) sBias[t] = g_biasv[b * PD + h * HD + t];

    const __half* gA_hi = g_Ahi + ((size_t)(b * NS + stile * 64)) * TD;
    const __half* gA_lo = g_Alo + ((size_t)(b * NS + stile * 64)) * TD;
    const __half* gC    = g_Cf  + (size_t)(b * NH + h) * TD * HD;

    auto loadStage = [&](int s, int kk) {
        char* base = smem + s * MSTG;
        #pragma unroll
        for (int i = 0; i < 2; i++) {
            int cid = t + i * 256, m = cid >> 3, c = cid & 7;
            int cc = c ^ (m & 7);
            cpa16(base + m * 128 + cc * 16,        gA_hi + (size_t)m * TD + kk + c * 8);
            cpa16(base + 8192 + m * 128 + cc * 16, gA_lo + (size_t)m * TD + kk + c * 8);
        }
        #pragma unroll
        for (int i = 0; i < 4; i++) {
            int cid = t + i * 256, k = cid >> 4, c = cid & 15;
            int cc = (c & 8) | ((c & 7) ^ (k & 7));
            cpa16(base + 16384 + k * 256 + cc * 16, gC + (size_t)(kk + k) * HD + c * 8);
        }
    };

    float acc[8][4];
    #pragma unroll
    for (int j = 0; j < 8; j++)
        #pragma unroll
        for (int q = 0; q < 4; q++) acc[j][q] = 0.f;

    int mA = wm * 16 + (l & 15);
    int selA = l >> 4;
    int aRowOff = mA * 128, aX = mA & 7;
    int kb = ((l >> 3) & 1) * 8 + (l & 7);
    int cpB[4];
    #pragma unroll
    for (int q = 0; q < 4; q++) {
        int c = wn * 8 + q * 2 + (l >> 4);
        cpB[q] = (c & 8) | ((c & 7) ^ (l & 7));
    }

    loadStage(0, 0);
    CP_COMMIT();

    for (int it = 0; it < 16; ++it) {
        if (it + 1 < 16) loadStage((it + 1) & 1, (it + 1) * 64);
        CP_COMMIT();
        CP_WAIT1();
        __syncthreads();
        char* base = smem + (it & 1) * MSTG;
        #pragma unroll
        for (int ks = 0; ks < 4; ++ks) {
            unsigned ahi[4], alo[4];
            int aoff = aRowOff + (((ks * 2 + selA) ^ aX) << 4);
            ldsm4(ahi, base + aoff);
            ldsm4(alo, base + 8192 + aoff);
            unsigned bf[16];
            #pragma unroll
            for (int q = 0; q < 4; q++) {
                int off = (ks * 16 + kb) * 256 + cpB[q] * 16;
                ldsm4t(&bf[q * 4], base + 16384 + off);
            }
            #pragma unroll
            for (int j = 0; j < 8; j++) {
                mma_f16(acc[j], ahi, &bf[j * 2]);
                mma_f16(acc[j], alo, &bf[j * 2]);
            }
        }
        __syncthreads();
    }

    // ---- epilogue: +bias, per-head softmax over n (BN=128 = all states) ----
    int r0 = wm * 16 + (l >> 2);
    int cb = wn * 64 + (l & 3) * 2;
    #pragma unroll
    for (int j = 0; j < 8; j++) {
        float b0 = sBias[cb + j * 8], b1 = sBias[cb + j * 8 + 1];
        acc[j][0] += b0; acc[j][1] += b1; acc[j][2] += b0; acc[j][3] += b1;
    }
    float mx0 = -1e30f, mx8 = -1e30f;
    #pragma unroll
    for (int j = 0; j < 8; j++) {
        mx0 = fmaxf(mx0, fmaxf(acc[j][0], acc[j][1]));
        mx8 = fmaxf(mx8, fmaxf(acc[j][2], acc[j][3]));
    }
    mx0 = fmaxf(mx0, __shfl_xor_sync(~0u, mx0, 1));
    mx0 = fmaxf(mx0, __shfl_xor_sync(~0u, mx0, 2));
    mx8 = fmaxf(mx8, __shfl_xor_sync(~0u, mx8, 1));
    mx8 = fmaxf(mx8, __shfl_xor_sync(~0u, mx8, 2));
    if ((l & 3) == 0) { sMax[r0][wn] = mx0; sMax[r0 + 8][wn] = mx8; }
    __syncthreads();
    float M0 = fmaxf(sMax[r0][0], sMax[r0][1]);
    float M8 = fmaxf(sMax[r0 + 8][0], sMax[r0 + 8][1]);
    float s0 = 0.f, s8 = 0.f;
    #pragma unroll
    for (int j = 0; j < 8; j++) {
        acc[j][0] = __expf(acc[j][0] - M0); s0 += acc[j][0];
        acc[j][1] = __expf(acc[j][1] - M0); s0 += acc[j][1];
        acc[j][2] = __expf(acc[j][2] - M8); s8 += acc[j][2];
        acc[j][3] = __expf(acc[j][3] - M8); s8 += acc[j][3];
    }
    s0 += __shfl_xor_sync(~0u, s0, 1); s0 += __shfl_xor_sync(~0u, s0, 2);
    s8 += __shfl_xor_sync(~0u, s8, 1); s8 += __shfl_xor_sync(~0u, s8, 2);
    if ((l & 3) == 0) { sSum[r0][wn] = s0; sSum[r0 + 8][wn] = s8; }
    __syncthreads();
    float inv0 = 1.f / (sSum[r0][0] + sSum[r0][1]);
    float inv8 = 1.f / (sSum[r0 + 8][0] + sSum[r0 + 8][1]);
    __half* wout = g_w + ((size_t)(b * NH + h) * NS + stile * 64) * NN;
    #pragma unroll
    for (int j = 0; j < 8; j++) {
        *(__half2*)(wout + (size_t)r0 * NN + cb + j * 8) =
            __floats2half2_rn(acc[j][0] * inv0, acc[j][1] * inv0);
        *(__half2*)(wout + (size_t)(r0 + 8) * NN + cb + j * 8) =
            __floats2half2_rn(acc[j][2] * inv8, acc[j][3] * inv8);
    }
}

// ============================================================================
// L6 meanent: head-mean + entropy; LAST block reduces all partials (no fin)
// ============================================================================
__global__ void meanent_kernel(float* __restrict__ out_rout, float* __restrict__ out_loss) {
    int t = threadIdx.x, w = t >> 5, l = t & 31;
    int row = blockIdx.x * 8 + w;
    int b = row >> 12, s = row & 4095;
    size_t hs = (size_t)NS * NN;
    size_t base = ((size_t)(b * NH) * NS + s) * NN + l * 4;
    float a0 = 0.f, a1 = 0.f, a2 = 0.f, a3 = 0.f;
    #pragma unroll
    for (int h = 0; h < NH; h++) {
        const __half2* p = (const __half2*)(g_w + base + h * hs);
        float2 x = __half22float2(p[0]);
        float2 y = __half22float2(p[1]);
        a0 += x.x; a1 += x.y; a2 += y.x; a3 += y.y;
    }
    float4 v = make_float4(a0 * 0.25f, a1 * 0.25f, a2 * 0.25f, a3 * 0.25f);
    *(float4*)(out_rout + (size_t)row * NN + l * 4) = v;
    float c = v.x * __logf(v.x + 1e-8f) + v.y * __logf(v.y + 1e-8f)
            + v.z * __logf(v.z + 1e-8f) + v.w * __logf(v.w + 1e-8f);
    #pragma unroll
    for (int o = 16; o; o >>= 1) c += __shfl_xor_sync(~0u, c, o);
    __shared__ float red[8];
    __shared__ int isLast;
    if (l == 0) red[w] = c;
    __syncthreads();
    if (t == 0) {
        float s2 = 0.f;
        #pragma unroll
        for (int i = 0; i < 8; i++) s2 += red[i];
        g_entpart[blockIdx.x] = s2;
        __threadfence();
        unsigned old = atomicAdd(&g_fincnt, 1u);
        isLast = (old == 2047u);
    }
    __syncthreads();
    if (isLast) {
        float s2 = 0.f;
        #pragma unroll
        for (int i = 0; i < 8; i++) s2 += g_entpart[i * 256 + t];
        #pragma unroll
        for (int o = 16; o; o >>= 1) s2 += __shfl_xor_sync(~0u, s2, o);
        if (l == 0) red[w] = s2;
        __syncthreads();
        if (t == 0) {
            float tot = 0.f;
            #pragma unroll
            for (int i = 0; i < 8; i++) tot += red[i];
            out_loss[0] = tot * (0.01f / (float)NTOK);
        }
    }
}

// ---------------- launch (single stream) -------------------------------------
extern "C" void kernel_launch(void* const* d_in, const int* in_sizes, int n_in,
                              void* d_out, int out_size) {
    (void)in_sizes; (void)n_in; (void)out_size;
    const float* tokens = (const float*)d_in[0];
    const float* states = (const float*)d_in[1];
    const float* ln_t_g = (const float*)d_in[2];
    const float* ln_t_b = (const float*)d_in[3];
    const float* ln_s_g = (const float*)d_in[4];
    const float* ln_s_b = (const float*)d_in[5];
    const float* Wq     = (const float*)d_in[6];
    const float* bq     = (const float*)d_in[7];
    const float* Wk     = (const float*)d_in[8];
    const float* bk     = (const float*)d_in[9];
    const float* temp   = (const float*)d_in[10];
    float* out = (float*)d_out;

    cudaFuncSetAttribute(main_kernel, cudaFuncAttributeMaxDynamicSharedMemorySize, 2 * MSTG);

    prepA_kernel<<<NB * NN + 32, 256>>>(states, ln_s_g, ln_s_b, Wq, ln_t_b);
    prepB_kernel<<<34, 256>>>(Wk, bk, bq);
    tokln_kernel<<<2048, 256>>>(tokens, out);
    prepC_kernel<<<264, 256>>>(Wq, ln_t_g, temp);
    main_kernel<<<dim3(64, 4, 4), 256, 2 * MSTG>>>();            // profiled slot 5
    meanent_kernel<<<2048, 256>>>(out + (size_t)NTOK * TD,
                                  out + (size_t)NTOK * TD + (size_t)NTOK * NN);
}

// round 17
// speedup vs baseline: 1.3846x; 1.1133x over previous
#include <cuda_runtime.h>
#include <cuda_bf16.h>
#include <cuda_fp16.h>
#include <math.h>

#define NB 4
#define NS 4096
#define NN 128
#define TD 1024
#define SD 512
#define PD 512
#define NH 4
#define HD 128
#define NTOK (NB*NS)

// ---------------- static device scratch (no runtime alloc allowed) ----------
__device__ __align__(16) __half g_A[NTOK*TD];                 // 32 MB (fp16 tokens-LN)
__device__ __align__(16) float g_sn[NB*NN*SD];                // 1 MB
__device__ __align__(16) float g_kfull[NB*NN*PD];             // 1 MB
__device__ float g_qpart[16*PD];
__device__ float g_qconst[PD];
__device__ float g_biasv[NB*PD];
__device__ __align__(16) __half g_Cf[NB*NH*TD*HD];            // 4 MB [b][h][k][n] fp16
__device__ __align__(16) __half g_w[(size_t)NB*NH*NS*NN];     // 16 MB (fp16 weights)
__device__ float g_entpart[2048];
__device__ unsigned g_fincnt;

// ---------------- PTX helpers ----------------------------------------------
__device__ __forceinline__ void ldsm4(unsigned r[4], const void* p) {
    unsigned a = (unsigned)__cvta_generic_to_shared(p);
    asm volatile("ldmatrix.sync.aligned.m8n8.x4.shared.b16 {%0,%1,%2,%3}, [%4];"
                 : "=r"(r[0]), "=r"(r[1]), "=r"(r[2]), "=r"(r[3]) : "r"(a));
}
__device__ __forceinline__ void ldsm4t(unsigned* r, const void* p) {
    unsigned a = (unsigned)__cvta_generic_to_shared(p);
    asm volatile("ldmatrix.sync.aligned.m8n8.x4.trans.shared.b16 {%0,%1,%2,%3}, [%4];"
                 : "=r"(r[0]), "=r"(r[1]), "=r"(r[2]), "=r"(r[3]) : "r"(a));
}
__device__ __forceinline__ void mma_f16(float c[4], const unsigned a[4], const unsigned b[2]) {
    asm volatile("mma.sync.aligned.m16n8k16.row.col.f32.f16.f16.f32 "
                 "{%0,%1,%2,%3},{%4,%5,%6,%7},{%8,%9},{%0,%1,%2,%3};"
                 : "+f"(c[0]), "+f"(c[1]), "+f"(c[2]), "+f"(c[3])
                 : "r"(a[0]), "r"(a[1]), "r"(a[2]), "r"(a[3]), "r"(b[0]), "r"(b[1]));
}
__device__ __forceinline__ void cpa16(void* s, const void* g) {
    unsigned sa = (unsigned)__cvta_generic_to_shared(s);
    asm volatile("cp.async.cg.shared.global [%0],[%1],16;" :: "r"(sa), "l"(g) : "memory");
}
#define CP_COMMIT() asm volatile("cp.async.commit_group;" ::: "memory")
#define CP_WAIT1()  asm volatile("cp.async.wait_group 1;"  ::: "memory")

// ============================================================================
// L1 prepA: state LN (512 blocks) | qconst split-K partials (32 blocks)
// ============================================================================
__global__ void prepA_kernel(const float* __restrict__ st,
                             const float* __restrict__ lnsg, const float* __restrict__ lnsb,
                             const float* __restrict__ Wq, const float* __restrict__ bt) {
    int bid = blockIdx.x, t = threadIdx.x;
    if (bid == 0 && t == 0) g_fincnt = 0;
    if (bid < NB * NN) {
        int row = bid;
        const float2* rp = (const float2*)(st + (size_t)row * SD);
        float2 x = rp[t];
        __shared__ float red2[8];
        __shared__ float z_mu, z_rstd;
        float p = x.x + x.y;
        #pragma unroll
        for (int o = 16; o; o >>= 1) p += __shfl_xor_sync(~0u, p, o);
        if ((t & 31) == 0) red2[t >> 5] = p;
        __syncthreads();
        if (t == 0) { float s = 0;
            #pragma unroll
            for (int i = 0; i < 8; i++) s += red2[i]; z_mu = s * (1.f / SD); }
        __syncthreads();
        float mu = z_mu;
        float d0 = x.x - mu, d1 = x.y - mu;
        p = d0*d0 + d1*d1;
        #pragma unroll
        for (int o = 16; o; o >>= 1) p += __shfl_xor_sync(~0u, p, o);
        if ((t & 31) == 0) red2[t >> 5] = p;
        __syncthreads();
        if (t == 0) { float s = 0;
            #pragma unroll
            for (int i = 0; i < 8; i++) s += red2[i]; z_rstd = rsqrtf(s * (1.f / SD) + 1e-5f); }
        __syncthreads();
        float r = z_rstd;
        int c = t * 2;
        float2 y;
        y.x = d0 * r * lnsg[c]     + lnsb[c];
        y.y = d1 * r * lnsg[c + 1] + lnsb[c + 1];
        ((float2*)(g_sn + (size_t)row * SD))[t] = y;
    } else {
        int idx = bid - NB * NN;             // 0..31
        int p = (idx & 1) * 256 + t;
        int k0 = (idx >> 1) * 64;
        float acc = 0.f;
        #pragma unroll 8
        for (int kk = 0; kk < 64; kk++) acc += bt[k0 + kk] * Wq[(size_t)(k0 + kk) * PD + p];
        g_qpart[(idx >> 1) * PD + p] = acc;
    }
}

// ============================================================================
// L2 prepB: kproj (32 blocks) | qreduce (2 blocks)
// ============================================================================
__global__ void prepB_kernel(const float* __restrict__ Wk, const float* __restrict__ bk,
                             const float* __restrict__ bq) {
    int bid = blockIdx.x, t = threadIdx.x;
    if (bid < 32) {
        int r0 = (bid & 7) * 64, p0 = (bid >> 3) * 128;
        __shared__ float sSn[64 * 33];
        __shared__ float sWk[32 * 128];
        int tr = t >> 4, tp = t & 15;
        float acc[4][8];
        #pragma unroll
        for (int i = 0; i < 4; i++)
            #pragma unroll
            for (int j = 0; j < 8; j++) acc[i][j] = 0.f;
        for (int c0 = 0; c0 < SD; c0 += 32) {
            for (int idx = t; idx < 64 * 32; idx += 256) {
                int rr = idx >> 5, cc = idx & 31;
                sSn[rr * 33 + cc] = g_sn[(size_t)(r0 + rr) * SD + c0 + cc];
            }
            for (int idx = t; idx < 32 * 128; idx += 256) {
                int cc = idx >> 7, pp = idx & 127;
                sWk[cc * 128 + pp] = Wk[(size_t)(c0 + cc) * PD + p0 + pp];
            }
            __syncthreads();
            for (int cc = 0; cc < 32; cc++) {
                float a0 = sSn[(tr*4+0)*33+cc], a1 = sSn[(tr*4+1)*33+cc];
                float a2 = sSn[(tr*4+2)*33+cc], a3 = sSn[(tr*4+3)*33+cc];
                #pragma unroll
                for (int pp = 0; pp < 8; pp++) {
                    float w = sWk[cc * 128 + tp * 8 + pp];
                    acc[0][pp] += a0 * w; acc[1][pp] += a1 * w;
                    acc[2][pp] += a2 * w; acc[3][pp] += a3 * w;
                }
            }
            __syncthreads();
        }
        #pragma unroll
        for (int rr = 0; rr < 4; rr++)
            #pragma unroll
            for (int pp = 0; pp < 8; pp++) {
                int p = p0 + tp * 8 + pp;
                g_kfull[(size_t)(r0 + tr*4 + rr) * PD + p] = acc[rr][pp] + bk[p];
            }
    } else {
        int p = (bid - 32) * 256 + t;
        float s = bq[p];
        #pragma unroll
        for (int j = 0; j < 16; j++) s += g_qpart[j * PD + p];
        g_qconst[p] = s;
    }
}

// ============================================================================
// L3 tokln: token LN -> fp16 + passthrough, warp-per-row
// ============================================================================
__global__ void tokln_kernel(const float* __restrict__ tok, float* __restrict__ out_tok) {
    int t = threadIdx.x, w = t >> 5, l = t & 31;
    int row = blockIdx.x * 8 + w;
    const float4* rp = (const float4*)(tok + (size_t)row * TD);
    float4* wp = (float4*)(out_tok + (size_t)row * TD);
    float4 x[8];
    #pragma unroll
    for (int j = 0; j < 8; j++) x[j] = rp[j * 32 + l];
    #pragma unroll
    for (int j = 0; j < 8; j++) wp[j * 32 + l] = x[j];   // passthrough
    float p = 0.f;
    #pragma unroll
    for (int j = 0; j < 8; j++) p += (x[j].x + x[j].y) + (x[j].z + x[j].w);
    #pragma unroll
    for (int o = 16; o; o >>= 1) p += __shfl_xor_sync(~0u, p, o);
    float mu = p * (1.f / TD);
    float v = 0.f;
    #pragma unroll
    for (int j = 0; j < 8; j++) {
        float a = x[j].x - mu, b = x[j].y - mu, c = x[j].z - mu, d = x[j].w - mu;
        v += a*a + b*b + c*c + d*d;
    }
    #pragma unroll
    for (int o = 16; o; o >>= 1) v += __shfl_xor_sync(~0u, v, o);
    float r = rsqrtf(v * (1.f / TD) + 1e-5f);
    #pragma unroll
    for (int j = 0; j < 8; j++) {
        union { __half h[4]; uint2 u; } hz;
        hz.h[0] = __float2half_rn((x[j].x - mu) * r);
        hz.h[1] = __float2half_rn((x[j].y - mu) * r);
        hz.h[2] = __float2half_rn((x[j].z - mu) * r);
        hz.h[3] = __float2half_rn((x[j].w - mu) * r);
        *reinterpret_cast<uint2*>(&g_A[(size_t)row * TD + (j * 32 + l) * 4]) = hz.u;
    }
}

// ============================================================================
// L4 prepC: cbuild 4kx8n register-blocked (256 blocks), single fp16 C out
// | biasv (8 blocks)
// ============================================================================
__global__ void prepC_kernel(const float* __restrict__ Wq, const float* __restrict__ gt,
                             const float* __restrict__ temp) {
    int bid = blockIdx.x, t = threadIdx.x;
    if (bid < 256) {
        int kt = bid & 15, h = (bid >> 4) & 3, b = bid >> 6;
        int k0 = kt * 64;
        float invt = 1.f / fmaxf(temp[0], 0.1f);
        __shared__ float sWg[64 * 33];
        __shared__ float sKp[32 * 133];
        int tr = t >> 4, tp = t & 15;
        float acc[4][8];
        #pragma unroll
        for (int i = 0; i < 4; i++)
            #pragma unroll
            for (int j = 0; j < 8; j++) acc[i][j] = 0.f;
        int dd0 = t & 31, grp = t >> 5;
        for (int dc = 0; dc < HD; dc += 32) {
            #pragma unroll
            for (int kk = grp; kk < 64; kk += 8)
                sWg[kk * 33 + dd0] = Wq[(size_t)(k0 + kk) * PD + h * HD + dc + dd0] * gt[k0 + kk];
            #pragma unroll
            for (int n = grp; n < 128; n += 8)
                sKp[dd0 * 133 + n] = g_kfull[((size_t)(b * NN + n)) * PD + h * HD + dc + dd0] * invt;
            __syncthreads();
            #pragma unroll
            for (int dd = 0; dd < 32; dd++) {
                float a0 = sWg[(tr * 4 + 0) * 33 + dd];
                float a1 = sWg[(tr * 4 + 1) * 33 + dd];
                float a2 = sWg[(tr * 4 + 2) * 33 + dd];
                float a3 = sWg[(tr * 4 + 3) * 33 + dd];
                #pragma unroll
                for (int pp = 0; pp < 8; pp++) {
                    float w = sKp[dd * 133 + tp + 16 * pp];
                    acc[0][pp] += a0 * w; acc[1][pp] += a1 * w;
                    acc[2][pp] += a2 * w; acc[3][pp] += a3 * w;
                }
            }
            __syncthreads();
        }
        #pragma unroll
        for (int i = 0; i < 4; i++) {
            int k = k0 + tr * 4 + i;
            size_t rowb = ((size_t)(b * NH + h) * TD + k) * HD;
            #pragma unroll
            for (int pp = 0; pp < 8; pp++) {
                int n = tp + 16 * pp;
                g_Cf[rowb + n] = __float2half_rn(acc[i][pp]);
            }
        }
    } else {
        int gi = (bid - 256) * 256 + t;
        int b = gi >> 9, r = gi & 511;
        int h = r >> 7, n = r & 127;
        float invt = 1.f / fmaxf(temp[0], 0.1f);
        const float* kp = &g_kfull[((size_t)(b * NN + n)) * PD + h * HD];
        const float* qc = &g_qconst[h * HD];
        float acc = 0.f;
        for (int d = 0; d < HD; d++) acc += qc[d] * kp[d];
        g_biasv[b * PD + r] = acc * invt;
    }
}

// ============================================================================
// L5 main: single-stream fp16 GEMM + per-head softmax
// grid (stile=64, h=4, b=4), block 256 (8 warps: 4m x 2n), BM=64 BN=128 BK=64
// stage 24KB: A 8K | Cf 16K;  2 stages = 48KB  (2 CTA/SM)
// ============================================================================
#define MSTG 24576
__global__ void __launch_bounds__(256, 2) main_kernel() {
    extern __shared__ char smem[];
    int stile = blockIdx.x, h = blockIdx.y, b = blockIdx.z;
    int t = threadIdx.x, l = t & 31, w = t >> 5;
    int wm = w >> 1, wn = w & 1;
    __shared__ float sBias[128];
    __shared__ float sMax[64][2], sSum[64][2];
    if (t < 128) sBias[t] = g_biasv[b * PD + h * HD + t];

    const __half* gA = g_A  + ((size_t)(b * NS + stile * 64)) * TD;
    const __half* gC = g_Cf + (size_t)(b * NH + h) * TD * HD;

    auto loadStage = [&](int s, int kk) {
        char* base = smem + s * MSTG;
        #pragma unroll
        for (int i = 0; i < 2; i++) {
            int cid = t + i * 256, m = cid >> 3, c = cid & 7;
            int cc = c ^ (m & 7);
            cpa16(base + m * 128 + cc * 16, gA + (size_t)m * TD + kk + c * 8);
        }
        #pragma unroll
        for (int i = 0; i < 4; i++) {
            int cid = t + i * 256, k = cid >> 4, c = cid & 15;
            int cc = (c & 8) | ((c & 7) ^ (k & 7));
            cpa16(base + 8192 + k * 256 + cc * 16, gC + (size_t)(kk + k) * HD + c * 8);
        }
    };

    float acc[8][4];
    #pragma unroll
    for (int j = 0; j < 8; j++)
        #pragma unroll
        for (int q = 0; q < 4; q++) acc[j][q] = 0.f;

    int mA = wm * 16 + (l & 15);
    int selA = l >> 4;
    int aRowOff = mA * 128, aX = mA & 7;
    int kb = ((l >> 3) & 1) * 8 + (l & 7);
    int cpB[4];
    #pragma unroll
    for (int q = 0; q < 4; q++) {
        int c = wn * 8 + q * 2 + (l >> 4);
        cpB[q] = (c & 8) | ((c & 7) ^ (l & 7));
    }

    loadStage(0, 0);
    CP_COMMIT();

    for (int it = 0; it < 16; ++it) {
        if (it + 1 < 16) loadStage((it + 1) & 1, (it + 1) * 64);
        CP_COMMIT();
        CP_WAIT1();
        __syncthreads();
        char* base = smem + (it & 1) * MSTG;
        #pragma unroll
        for (int ks = 0; ks < 4; ++ks) {
            unsigned af[4];
            int aoff = aRowOff + (((ks * 2 + selA) ^ aX) << 4);
            ldsm4(af, base + aoff);
            unsigned bf[16];
            #pragma unroll
            for (int q = 0; q < 4; q++) {
                int off = (ks * 16 + kb) * 256 + cpB[q] * 16;
                ldsm4t(&bf[q * 4], base + 8192 + off);
            }
            #pragma unroll
            for (int j = 0; j < 8; j++)
                mma_f16(acc[j], af, &bf[j * 2]);
        }
        __syncthreads();
    }

    // ---- epilogue: +bias, per-head softmax over n (BN=128 = all states) ----
    int r0 = wm * 16 + (l >> 2);
    int cb = wn * 64 + (l & 3) * 2;
    #pragma unroll
    for (int j = 0; j < 8; j++) {
        float b0 = sBias[cb + j * 8], b1 = sBias[cb + j * 8 + 1];
        acc[j][0] += b0; acc[j][1] += b1; acc[j][2] += b0; acc[j][3] += b1;
    }
    float mx0 = -1e30f, mx8 = -1e30f;
    #pragma unroll
    for (int j = 0; j < 8; j++) {
        mx0 = fmaxf(mx0, fmaxf(acc[j][0], acc[j][1]));
        mx8 = fmaxf(mx8, fmaxf(acc[j][2], acc[j][3]));
    }
    mx0 = fmaxf(mx0, __shfl_xor_sync(~0u, mx0, 1));
    mx0 = fmaxf(mx0, __shfl_xor_sync(~0u, mx0, 2));
    mx8 = fmaxf(mx8, __shfl_xor_sync(~0u, mx8, 1));
    mx8 = fmaxf(mx8, __shfl_xor_sync(~0u, mx8, 2));
    if ((l & 3) == 0) { sMax[r0][wn] = mx0; sMax[r0 + 8][wn] = mx8; }
    __syncthreads();
    float M0 = fmaxf(sMax[r0][0], sMax[r0][1]);
    float M8 = fmaxf(sMax[r0 + 8][0], sMax[r0 + 8][1]);
    float s0 = 0.f, s8 = 0.f;
    #pragma unroll
    for (int j = 0; j < 8; j++) {
        acc[j][0] = __expf(acc[j][0] - M0); s0 += acc[j][0];
        acc[j][1] = __expf(acc[j][1] - M0); s0 += acc[j][1];
        acc[j][2] = __expf(acc[j][2] - M8); s8 += acc[j][2];
        acc[j][3] = __expf(acc[j][3] - M8); s8 += acc[j][3];
    }
    s0 += __shfl_xor_sync(~0u, s0, 1); s0 += __shfl_xor_sync(~0u, s0, 2);
    s8 += __shfl_xor_sync(~0u, s8, 1); s8 += __shfl_xor_sync(~0u, s8, 2);
    if ((l & 3) == 0) { sSum[r0][wn] = s0; sSum[r0 + 8][wn] = s8; }
    __syncthreads();
    float inv0 = 1.f / (sSum[r0][0] + sSum[r0][1]);
    float inv8 = 1.f / (sSum[r0 + 8][0] + sSum[r0 + 8][1]);
    __half* wout = g_w + ((size_t)(b * NH + h) * NS + stile * 64) * NN;
    #pragma unroll
    for (int j = 0; j < 8; j++) {
        *(__half2*)(wout + (size_t)r0 * NN + cb + j * 8) =
            __floats2half2_rn(acc[j][0] * inv0, acc[j][1] * inv0);
        *(__half2*)(wout + (size_t)(r0 + 8) * NN + cb + j * 8) =
            __floats2half2_rn(acc[j][2] * inv8, acc[j][3] * inv8);
    }
}

// ============================================================================
// L6 meanent: head-mean + entropy; LAST block reduces all partials (no fin)
// ============================================================================
__global__ void meanent_kernel(float* __restrict__ out_rout, float* __restrict__ out_loss) {
    int t = threadIdx.x, w = t >> 5, l = t & 31;
    int row = blockIdx.x * 8 + w;
    int b = row >> 12, s = row & 4095;
    size_t hs = (size_t)NS * NN;
    size_t base = ((size_t)(b * NH) * NS + s) * NN + l * 4;
    float a0 = 0.f, a1 = 0.f, a2 = 0.f, a3 = 0.f;
    #pragma unroll
    for (int h = 0; h < NH; h++) {
        const __half2* p = (const __half2*)(g_w + base + h * hs);
        float2 x = __half22float2(p[0]);
        float2 y = __half22float2(p[1]);
        a0 += x.x; a1 += x.y; a2 += y.x; a3 += y.y;
    }
    float4 v = make_float4(a0 * 0.25f, a1 * 0.25f, a2 * 0.25f, a3 * 0.25f);
    *(float4*)(out_rout + (size_t)row * NN + l * 4) = v;
    float c = v.x * __logf(v.x + 1e-8f) + v.y * __logf(v.y + 1e-8f)
            + v.z * __logf(v.z + 1e-8f) + v.w * __logf(v.w + 1e-8f);
    #pragma unroll
    for (int o = 16; o; o >>= 1) c += __shfl_xor_sync(~0u, c, o);
    __shared__ float red[8];
    __shared__ int isLast;
    if (l == 0) red[w] = c;
    __syncthreads();
    if (t == 0) {
        float s2 = 0.f;
        #pragma unroll
        for (int i = 0; i < 8; i++) s2 += red[i];
        g_entpart[blockIdx.x] = s2;
        __threadfence();
        unsigned old = atomicAdd(&g_fincnt, 1u);
        isLast = (old == 2047u);
    }
    __syncthreads();
    if (isLast) {
        float s2 = 0.f;
        #pragma unroll
        for (int i = 0; i < 8; i++) s2 += g_entpart[i * 256 + t];
        #pragma unroll
        for (int o = 16; o; o >>= 1) s2 += __shfl_xor_sync(~0u, s2, o);
        if (l == 0) red[w] = s2;
        __syncthreads();
        if (t == 0) {
            float tot = 0.f;
            #pragma unroll
            for (int i = 0; i < 8; i++) tot += red[i];
            out_loss[0] = tot * (0.01f / (float)NTOK);
        }
    }
}

// ---------------- launch (single stream) -------------------------------------
extern "C" void kernel_launch(void* const* d_in, const int* in_sizes, int n_in,
                              void* d_out, int out_size) {
    (void)in_sizes; (void)n_in; (void)out_size;
    const float* tokens = (const float*)d_in[0];
    const float* states = (const float*)d_in[1];
    const float* ln_t_g = (const float*)d_in[2];
    const float* ln_t_b = (const float*)d_in[3];
    const float* ln_s_g = (const float*)d_in[4];
    const float* ln_s_b = (const float*)d_in[5];
    const float* Wq     = (const float*)d_in[6];
    const float* bq     = (const float*)d_in[7];
    const float* Wk     = (const float*)d_in[8];
    const float* bk     = (const float*)d_in[9];
    const float* temp   = (const float*)d_in[10];
    float* out = (float*)d_out;

    cudaFuncSetAttribute(main_kernel, cudaFuncAttributeMaxDynamicSharedMemorySize, 2 * MSTG);

    prepA_kernel<<<NB * NN + 32, 256>>>(states, ln_s_g, ln_s_b, Wq, ln_t_b);
    prepB_kernel<<<34, 256>>>(Wk, bk, bq);
    tokln_kernel<<<2048, 256>>>(tokens, out);
    prepC_kernel<<<264, 256>>>(Wq, ln_t_g, temp);
    main_kernel<<<dim3(64, 4, 4), 256, 2 * MSTG>>>();            // profiled slot 5
    meanent_kernel<<<2048, 256>>>(out + (size_t)NTOK * TD,
                                  out + (size_t)NTOK * TD + (size_t)NTOK * NN);
}